// round 3
// baseline (speedup 1.0000x reference)
#include <cuda_runtime.h>
#include <math.h>

#define HIDDEN      512
#define BATCH       16384
#define NUM_LAYERS  8
#define NUM_OUTPUTS 16

#define BM 128
#define BN 128
#define BK 16
#define TM 8
#define TN 8
#define THREADS 256   // 16x16 thread tile grid

// Ping-pong activation buffers (device globals: allocation-free scratch)
__device__ __align__(16) float g_bufA[BATCH * HIDDEN];
__device__ __align__(16) float g_bufB[BATCH * HIDDEN];

// ---------------------------------------------------------------------------
// Pixel norm: x = z * rsqrt(mean(z^2, dim=1) + eps)
// One warp per row (512 floats = 128 float4s; 32 lanes x 4 float4).
// ---------------------------------------------------------------------------
__global__ void pixelnorm_kernel(const float* __restrict__ z,
                                 float* __restrict__ out) {
    int row  = blockIdx.x * blockDim.y + threadIdx.y;
    int lane = threadIdx.x;
    const float4* zr = reinterpret_cast<const float4*>(z + (size_t)row * HIDDEN);
    float4 v[4];
    float ss = 0.f;
#pragma unroll
    for (int i = 0; i < 4; i++) {
        v[i] = zr[lane + 32 * i];
        ss += v[i].x * v[i].x + v[i].y * v[i].y + v[i].z * v[i].z + v[i].w * v[i].w;
    }
#pragma unroll
    for (int off = 16; off > 0; off >>= 1)
        ss += __shfl_xor_sync(0xFFFFFFFFu, ss, off);
    float s = rsqrtf(ss * (1.0f / HIDDEN) + 1e-8f);
    float4* o = reinterpret_cast<float4*>(out + (size_t)row * HIDDEN);
#pragma unroll
    for (int i = 0; i < 4; i++) {
        float4 t = v[i];
        t.x *= s; t.y *= s; t.z *= s; t.w *= s;
        o[lane + 32 * i] = t;
    }
}

// ---------------------------------------------------------------------------
// Dense layer: Y[m][n] = lrelu( X[m][:] . W[n][:] * wscale + bias[n]*bscale ) * sqrt(2)
// X: [BATCH, HIDDEN] row-major. W: [HIDDEN(out), HIDDEN(in)] row-major (one layer).
// 128x128 block tile, BK=16, 8x8 per-thread register tile.
// BROADCAST: write 16 replicated copies straight into wp layout [B, 16, 512].
// ---------------------------------------------------------------------------
template <bool BROADCAST>
__global__ __launch_bounds__(THREADS)
void dense_kernel(const float* __restrict__ X,
                  const float* __restrict__ W,
                  const float* __restrict__ Bv,
                  float* __restrict__ Y) {
    // padded stride: 132 floats = 528 bytes, divisible by 16 -> float4-safe rows
    __shared__ __align__(16) float As[BK * (BM + 4)];
    __shared__ __align__(16) float Bs[BK * (BN + 4)];
    const int LDS = BM + 4;

    const int tid   = threadIdx.x;
    const int mBase = blockIdx.y * BM;
    const int nBase = blockIdx.x * BN;

    const int tr = tid >> 4;   // 0..15
    const int tc = tid & 15;   // 0..15

    float acc[TM][TN];
#pragma unroll
    for (int i = 0; i < TM; i++)
#pragma unroll
        for (int j = 0; j < TN; j++) acc[i][j] = 0.f;

    for (int kt = 0; kt < HIDDEN; kt += BK) {
        // Load A tile (128 rows x 16 k) and B tile (128 n-rows x 16 k),
        // transposed into smem: As[k][m], Bs[k][n]. 2 float4 per thread per tile.
#pragma unroll
        for (int t = 0; t < 2; t++) {
            int idx = tid + t * THREADS;       // 0..511
            int row = idx >> 2;                // 0..127
            int c4  = idx & 3;                 // 0..3  -> k = c4*4
            float4 av = *reinterpret_cast<const float4*>(
                X + (size_t)(mBase + row) * HIDDEN + kt + c4 * 4);
            float4 bv = *reinterpret_cast<const float4*>(
                W + (size_t)(nBase + row) * HIDDEN + kt + c4 * 4);
            int k0 = c4 * 4;
            As[(k0 + 0) * LDS + row] = av.x;
            As[(k0 + 1) * LDS + row] = av.y;
            As[(k0 + 2) * LDS + row] = av.z;
            As[(k0 + 3) * LDS + row] = av.w;
            Bs[(k0 + 0) * LDS + row] = bv.x;
            Bs[(k0 + 1) * LDS + row] = bv.y;
            Bs[(k0 + 2) * LDS + row] = bv.z;
            Bs[(k0 + 3) * LDS + row] = bv.w;
        }
        __syncthreads();

#pragma unroll
        for (int k = 0; k < BK; k++) {
            float4 a0 = *reinterpret_cast<const float4*>(&As[k * LDS + tr * TM]);
            float4 a1 = *reinterpret_cast<const float4*>(&As[k * LDS + tr * TM + 4]);
            float4 b0 = *reinterpret_cast<const float4*>(&Bs[k * LDS + tc * TN]);
            float4 b1 = *reinterpret_cast<const float4*>(&Bs[k * LDS + tc * TN + 4]);
            float a[TM] = {a0.x, a0.y, a0.z, a0.w, a1.x, a1.y, a1.z, a1.w};
            float b[TN] = {b0.x, b0.y, b0.z, b0.w, b1.x, b1.y, b1.z, b1.w};
#pragma unroll
            for (int i = 0; i < TM; i++)
#pragma unroll
                for (int j = 0; j < TN; j++)
                    acc[i][j] = fmaf(a[i], b[j], acc[i][j]);
        }
        __syncthreads();
    }

    // Epilogue: scale, bias, lrelu * sqrt(2)
    const float wscale = 0.01f / 22.627416997969522f;  // lr_mul / sqrt(512)
    const float bscale = 0.01f;
    const float gain   = 1.4142135623730951f;
    const float slope  = 0.2f;

    float bb[TN];
#pragma unroll
    for (int j = 0; j < TN; j++)
        bb[j] = Bv[nBase + tc * TN + j] * bscale;

#pragma unroll
    for (int i = 0; i < TM; i++) {
        int m = mBase + tr * TM + i;
        float4 o0, o1;
        float vals[TN];
#pragma unroll
        for (int j = 0; j < TN; j++) {
            float v = acc[i][j] * wscale + bb[j];
            v = (v > 0.f ? v : slope * v) * gain;
            vals[j] = v;
        }
        o0 = make_float4(vals[0], vals[1], vals[2], vals[3]);
        o1 = make_float4(vals[4], vals[5], vals[6], vals[7]);
        int n = nBase + tc * TN;
        if (BROADCAST) {
            // wp[m][r][n], r = 0..15
            float4* base = reinterpret_cast<float4*>(
                Y + (size_t)m * NUM_OUTPUTS * HIDDEN + n);
#pragma unroll
            for (int r = 0; r < NUM_OUTPUTS; r++) {
                base[0] = o0;
                base[1] = o1;
                base += HIDDEN / 4;
            }
        } else {
            float4* base = reinterpret_cast<float4*>(Y + (size_t)m * HIDDEN + n);
            base[0] = o0;
            base[1] = o1;
        }
    }
}

// ---------------------------------------------------------------------------
extern "C" void kernel_launch(void* const* d_in, const int* in_sizes, int n_in,
                              void* d_out, int out_size) {
    const float* z      = (const float*)d_in[0];
    const float* weight = (const float*)d_in[1];
    const float* bias   = (const float*)d_in[2];
    float* out          = (float*)d_out;

    float *bufA, *bufB;
    cudaGetSymbolAddress((void**)&bufA, g_bufA);
    cudaGetSymbolAddress((void**)&bufB, g_bufB);

    // 1) pixel norm: z -> bufA
    pixelnorm_kernel<<<BATCH / 8, dim3(32, 8)>>>(z, bufA);

    // 2) 8 dense layers, ping-pong; last layer writes broadcast output
    dim3 grid(HIDDEN / BN, BATCH / BM);  // (4, 128)
    for (int l = 0; l < NUM_LAYERS; l++) {
        const float* W = weight + (size_t)l * HIDDEN * HIDDEN;
        const float* B = bias + (size_t)l * HIDDEN;
        const float* src = (l & 1) ? bufB : bufA;
        float* dst       = (l & 1) ? bufA : bufB;
        if (l == NUM_LAYERS - 1) {
            dense_kernel<true><<<grid, THREADS>>>(src, W, B, out);
        } else {
            dense_kernel<false><<<grid, THREADS>>>(src, W, B, dst);
        }
    }
}

// round 6
// speedup vs baseline: 2.0828x; 2.0828x over previous
#include <cuda_runtime.h>
#include <cuda_bf16.h>
#include <stdint.h>
#include <math.h>

#define HIDDEN      512
#define BATCH       16384
#define NUM_LAYERS  8
#define NUM_OUTPUTS 16

#define BM 128
#define BN 128
#define BK 32                 // k per smem tile (32 bf16 = 64B per row)
#define KTILES (HIDDEN / BK)  // 16
#define THREADS 256

#define ROWSTRIDE 80          // 64B data + 16B pad -> conflict-free ldmatrix
#define MAT_BYTES (128 * ROWSTRIDE)   // 10240 per matrix tile
#define BUF_BYTES (4 * MAT_BYTES)     // xhi,xlo,whi,wlo = 40960
#define OFF_BIAS  0
#define OFF_TILES 512
#define SMEM_ALLOC (OFF_TILES + 2 * BUF_BYTES)   // 82432

#define WSCALE 4.419417382415922e-4f   // 0.01 / sqrt(512)
#define BSCALE 0.01f
#define GAIN   1.4142135623730951f
#define SLOPE  0.2f

// Device-global scratch (allocation-free): split activations + split weights
__device__ __align__(16) __nv_bfloat16 g_xhiA[BATCH * HIDDEN];
__device__ __align__(16) __nv_bfloat16 g_xloA[BATCH * HIDDEN];
__device__ __align__(16) __nv_bfloat16 g_xhiB[BATCH * HIDDEN];
__device__ __align__(16) __nv_bfloat16 g_xloB[BATCH * HIDDEN];
__device__ __align__(16) __nv_bfloat16 g_whi[NUM_LAYERS * HIDDEN * HIDDEN];
__device__ __align__(16) __nv_bfloat16 g_wlo[NUM_LAYERS * HIDDEN * HIDDEN];

// ---------------------------------------------------------------------------
// helpers
// ---------------------------------------------------------------------------
__device__ __forceinline__ uint32_t smem_u32(const void* p) {
    uint32_t a;
    asm("{ .reg .u64 t; cvta.to.shared.u64 t, %1; cvt.u32.u64 %0, t; }"
        : "=r"(a) : "l"(p));
    return a;
}
__device__ __forceinline__ float bf_round(float x) {
    return __bfloat162float(__float2bfloat16_rn(x));
}
// pack two fp32 -> bf16x2 (a in low half)
__device__ __forceinline__ uint32_t pack_bf2(float a, float b) {
    uint32_t r;
    asm("cvt.rn.bf16x2.f32 %0, %1, %2;" : "=r"(r) : "f"(b), "f"(a));
    return r;
}
__device__ __forceinline__ float lrelu_gain(float t) {
    return (t > 0.f ? t : SLOPE * t) * GAIN;
}

#define CP_ASYNC16(dst, src) \
    asm volatile("cp.async.cg.shared.global [%0], [%1], 16;" :: "r"(dst), "l"(src))
#define CP_COMMIT() asm volatile("cp.async.commit_group;" ::: "memory")
#define CP_WAIT1()  asm volatile("cp.async.wait_group 1;" ::: "memory")
#define CP_WAIT0()  asm volatile("cp.async.wait_group 0;" ::: "memory")

#define LDSM_X4(r0, r1, r2, r3, addr) \
    asm volatile("ldmatrix.sync.aligned.m8n8.x4.shared.b16 {%0,%1,%2,%3}, [%4];" \
                 : "=r"(r0), "=r"(r1), "=r"(r2), "=r"(r3) : "r"(addr))

#define MMA16816(c, a, b0, b1) \
    asm volatile("mma.sync.aligned.m16n8k16.row.col.f32.bf16.bf16.f32 " \
                 "{%0,%1,%2,%3}, {%4,%5,%6,%7}, {%8,%9}, {%0,%1,%2,%3};" \
                 : "+f"((c)[0]), "+f"((c)[1]), "+f"((c)[2]), "+f"((c)[3]) \
                 : "r"((a)[0]), "r"((a)[1]), "r"((a)[2]), "r"((a)[3]), \
                   "r"(b0), "r"(b1))

// ---------------------------------------------------------------------------
// Pre-split all layer weights: whi/wlo = split(W * wscale)
// ---------------------------------------------------------------------------
__global__ void split_w_kernel(const float* __restrict__ W,
                               __nv_bfloat16* __restrict__ whi,
                               __nv_bfloat16* __restrict__ wlo) {
    int base = (blockIdx.x * blockDim.x + threadIdx.x) * 4;
    float4 w = *reinterpret_cast<const float4*>(W + base);
    w.x *= WSCALE; w.y *= WSCALE; w.z *= WSCALE; w.w *= WSCALE;
    float h0 = bf_round(w.x), h1 = bf_round(w.y);
    float h2 = bf_round(w.z), h3 = bf_round(w.w);
    uint2 hi = make_uint2(pack_bf2(h0, h1), pack_bf2(h2, h3));
    uint2 lo = make_uint2(pack_bf2(w.x - h0, w.y - h1),
                          pack_bf2(w.z - h2, w.w - h3));
    *reinterpret_cast<uint2*>(&whi[base]) = hi;
    *reinterpret_cast<uint2*>(&wlo[base]) = lo;
}

// ---------------------------------------------------------------------------
// Pixel norm, writing split bf16 activations
// ---------------------------------------------------------------------------
__global__ void pixelnorm_split_kernel(const float* __restrict__ z,
                                       __nv_bfloat16* __restrict__ xhi,
                                       __nv_bfloat16* __restrict__ xlo) {
    int row  = blockIdx.x * blockDim.y + threadIdx.y;
    int lane = threadIdx.x;
    const float4* zr = reinterpret_cast<const float4*>(z + (size_t)row * HIDDEN);
    float4 v[4];
    float ss = 0.f;
#pragma unroll
    for (int i = 0; i < 4; i++) {
        v[i] = zr[lane + 32 * i];
        ss += v[i].x * v[i].x + v[i].y * v[i].y + v[i].z * v[i].z + v[i].w * v[i].w;
    }
#pragma unroll
    for (int off = 16; off > 0; off >>= 1)
        ss += __shfl_xor_sync(0xFFFFFFFFu, ss, off);
    float s = rsqrtf(ss * (1.0f / HIDDEN) + 1e-8f);
#pragma unroll
    for (int i = 0; i < 4; i++) {
        float x0 = v[i].x * s, x1 = v[i].y * s, x2 = v[i].z * s, x3 = v[i].w * s;
        float h0 = bf_round(x0), h1 = bf_round(x1);
        float h2 = bf_round(x2), h3 = bf_round(x3);
        int e = row * HIDDEN + (lane + 32 * i) * 4;
        *reinterpret_cast<uint2*>(&xhi[e]) =
            make_uint2(pack_bf2(h0, h1), pack_bf2(h2, h3));
        *reinterpret_cast<uint2*>(&xlo[e]) =
            make_uint2(pack_bf2(x0 - h0, x1 - h1), pack_bf2(x2 - h2, x3 - h3));
    }
}

// ---------------------------------------------------------------------------
// HMMA dense layer: acc = Xhi*Whi + Xhi*Wlo + Xlo*Whi (fp32 accum)
// Y = lrelu(acc + b*bscale)*sqrt(2); epilogue re-splits to bf16 hi/lo
// (or broadcasts fp32 to wp for the last layer).
// 256 threads = 8 warps (4 along M x 2 along N); warp tile 32x64.
// ---------------------------------------------------------------------------
template <bool BROADCAST>
__global__ __launch_bounds__(THREADS, 1)
void dense_mma(const __nv_bfloat16* __restrict__ Xhi,
               const __nv_bfloat16* __restrict__ Xlo,
               const __nv_bfloat16* __restrict__ Whi,
               const __nv_bfloat16* __restrict__ Wlo,
               const float* __restrict__ Bv,
               __nv_bfloat16* __restrict__ Yhi,
               __nv_bfloat16* __restrict__ Ylo,
               float* __restrict__ Yout) {
    extern __shared__ char smem[];
    const uint32_t sbase = smem_u32(smem);
    float* bias_s = reinterpret_cast<float*>(smem + OFF_BIAS);

    const int tid  = threadIdx.x;
    const int wid  = tid >> 5;
    const int lane = tid & 31;
    const int mBase = blockIdx.y * BM;
    const int nBase = blockIdx.x * BN;
    const int wmBase = (wid & 3) * 32;   // warp M offset in tile
    const int wnBase = (wid >> 2) * 64;  // warp N offset in tile

    if (tid < BN) bias_s[tid] = Bv[nBase + tid] * BSCALE;

    // ---- cp.async tile loader: 4 matrices (xhi,xlo,whi,wlo), 16B chunks ----
    // chunk id 0..511 per matrix: row = chunk>>2 (0..127), c = chunk&3.
    // smem: row*80 + c*16 ; global: (rowG*512 + kt*32 + c*8) bf16.
    const __nv_bfloat16* srcs[4] = {Xhi, Xlo, Whi, Wlo};

    auto load_tile = [&](int kt, int buf) {
        uint32_t base = sbase + OFF_TILES + buf * BUF_BYTES;
#pragma unroll
        for (int i = 0; i < 2; i++) {
            int chunk = tid + i * THREADS;
            int row = chunk >> 2;
            int c   = chunk & 3;
            uint32_t soff = (uint32_t)(row * ROWSTRIDE + c * 16);
#pragma unroll
            for (int m = 0; m < 4; m++) {
                int rowG = (m < 2 ? mBase : nBase) + row;
                const __nv_bfloat16* src =
                    srcs[m] + (size_t)rowG * HIDDEN + kt * BK + c * 8;
                CP_ASYNC16(base + m * MAT_BYTES + soff, src);
            }
        }
    };

    float c[2][8][4];
#pragma unroll
    for (int mi = 0; mi < 2; mi++)
#pragma unroll
        for (int ni = 0; ni < 8; ni++)
#pragma unroll
            for (int j = 0; j < 4; j++) c[mi][ni][j] = 0.f;

    load_tile(0, 0);
    CP_COMMIT();

    for (int kt = 0; kt < KTILES; kt++) {
        const int buf = kt & 1;
        if (kt < KTILES - 1) {
            load_tile(kt + 1, (kt + 1) & 1);
            CP_COMMIT();
            CP_WAIT1();
        } else {
            CP_WAIT0();
        }
        __syncthreads();

        const uint32_t xb = sbase + OFF_TILES + buf * BUF_BYTES;
        const uint32_t xhi_b = xb;
        const uint32_t xlo_b = xb + MAT_BYTES;
        const uint32_t whi_b = xb + 2 * MAT_BYTES;
        const uint32_t wlo_b = xb + 3 * MAT_BYTES;

#pragma unroll
        for (int s = 0; s < 2; s++) {          // two k16 steps per tile
            // A fragments (hi, lo) for mi = 0,1
            uint32_t a_hi[2][4], a_lo[2][4];
            {
                int arow  = wmBase + (lane & 15);
                int achnk = 2 * s + (lane >> 4);
                uint32_t aoff = (uint32_t)(arow * ROWSTRIDE + achnk * 16);
#pragma unroll
                for (int mi = 0; mi < 2; mi++) {
                    uint32_t ad = aoff + mi * 16 * ROWSTRIDE;
                    LDSM_X4(a_hi[mi][0], a_hi[mi][1], a_hi[mi][2], a_hi[mi][3],
                            xhi_b + ad);
                    LDSM_X4(a_lo[mi][0], a_lo[mi][1], a_lo[mi][2], a_lo[mi][3],
                            xlo_b + ad);
                }
            }
            // B fragments for 8 n8-tiles (hi, lo)
            uint32_t b_hi[8][2], b_lo[8][2];
            {
                int g = lane >> 3, r = lane & 7;
                int brow  = wnBase + (g >> 1) * 8 + r;
                int bchnk = 2 * s + (g & 1);
#pragma unroll
                for (int p = 0; p < 4; p++) {
                    uint32_t boff = (uint32_t)((brow + p * 16) * ROWSTRIDE + bchnk * 16);
                    LDSM_X4(b_hi[2 * p][0], b_hi[2 * p][1],
                            b_hi[2 * p + 1][0], b_hi[2 * p + 1][1], whi_b + boff);
                    LDSM_X4(b_lo[2 * p][0], b_lo[2 * p][1],
                            b_lo[2 * p + 1][0], b_lo[2 * p + 1][1], wlo_b + boff);
                }
            }
#pragma unroll
            for (int mi = 0; mi < 2; mi++)
#pragma unroll
                for (int ni = 0; ni < 8; ni++) {
                    MMA16816(c[mi][ni], a_hi[mi], b_hi[ni][0], b_hi[ni][1]);
                    MMA16816(c[mi][ni], a_hi[mi], b_lo[ni][0], b_lo[ni][1]);
                    MMA16816(c[mi][ni], a_lo[mi], b_hi[ni][0], b_hi[ni][1]);
                }
        }
        __syncthreads();
    }

    // ---- epilogue ----
    // C frag: lane -> rows (lane>>2), (lane>>2)+8; cols (lane&3)*2, +1
#pragma unroll
    for (int mi = 0; mi < 2; mi++) {
        int m0 = mBase + wmBase + mi * 16 + (lane >> 2);
#pragma unroll
        for (int ni = 0; ni < 8; ni++) {
            int n = nBase + wnBase + ni * 8 + (lane & 3) * 2;
            float v0 = lrelu_gain(c[mi][ni][0] + bias_s[n - nBase]);
            float v1 = lrelu_gain(c[mi][ni][1] + bias_s[n - nBase + 1]);
            float v2 = lrelu_gain(c[mi][ni][2] + bias_s[n - nBase]);
            float v3 = lrelu_gain(c[mi][ni][3] + bias_s[n - nBase + 1]);
            if (BROADCAST) {
                float2 p01 = make_float2(v0, v1);
                float2 p23 = make_float2(v2, v3);
                float* r0 = Yout + (size_t)m0 * NUM_OUTPUTS * HIDDEN + n;
                float* r1 = r0 + (size_t)8 * NUM_OUTPUTS * HIDDEN;
#pragma unroll
                for (int rep = 0; rep < NUM_OUTPUTS; rep++) {
                    *reinterpret_cast<float2*>(r0 + rep * HIDDEN) = p01;
                    *reinterpret_cast<float2*>(r1 + rep * HIDDEN) = p23;
                }
            } else {
                float h0 = bf_round(v0), h1 = bf_round(v1);
                float h2 = bf_round(v2), h3 = bf_round(v3);
                size_t e0 = (size_t)m0 * HIDDEN + n;
                size_t e1 = e0 + (size_t)8 * HIDDEN;
                *reinterpret_cast<uint32_t*>(&Yhi[e0]) = pack_bf2(h0, h1);
                *reinterpret_cast<uint32_t*>(&Ylo[e0]) = pack_bf2(v0 - h0, v1 - h1);
                *reinterpret_cast<uint32_t*>(&Yhi[e1]) = pack_bf2(h2, h3);
                *reinterpret_cast<uint32_t*>(&Ylo[e1]) = pack_bf2(v2 - h2, v3 - h3);
            }
        }
    }
}

// ---------------------------------------------------------------------------
extern "C" void kernel_launch(void* const* d_in, const int* in_sizes, int n_in,
                              void* d_out, int out_size) {
    const float* z      = (const float*)d_in[0];
    const float* weight = (const float*)d_in[1];
    const float* bias   = (const float*)d_in[2];
    float* out          = (float*)d_out;

    __nv_bfloat16 *xhiA, *xloA, *xhiB, *xloB, *whi, *wlo;
    cudaGetSymbolAddress((void**)&xhiA, g_xhiA);
    cudaGetSymbolAddress((void**)&xloA, g_xloA);
    cudaGetSymbolAddress((void**)&xhiB, g_xhiB);
    cudaGetSymbolAddress((void**)&xloB, g_xloB);
    cudaGetSymbolAddress((void**)&whi, g_whi);
    cudaGetSymbolAddress((void**)&wlo, g_wlo);

    cudaFuncSetAttribute(dense_mma<false>,
                         cudaFuncAttributeMaxDynamicSharedMemorySize, SMEM_ALLOC);
    cudaFuncSetAttribute(dense_mma<true>,
                         cudaFuncAttributeMaxDynamicSharedMemorySize, SMEM_ALLOC);

    // 1) split all weights (wscale folded)
    split_w_kernel<<<NUM_LAYERS * HIDDEN * HIDDEN / (256 * 4), 256>>>(weight, whi, wlo);

    // 2) pixel norm -> split activations (buffer A)
    pixelnorm_split_kernel<<<BATCH / 8, dim3(32, 8)>>>(z, xhiA, xloA);

    // 3) 8 HMMA dense layers, ping-pong; last broadcasts into wp
    dim3 grid(HIDDEN / BN, BATCH / BM);  // (4, 128)
    for (int l = 0; l < NUM_LAYERS; l++) {
        const __nv_bfloat16* Wh = whi + (size_t)l * HIDDEN * HIDDEN;
        const __nv_bfloat16* Wl = wlo + (size_t)l * HIDDEN * HIDDEN;
        const float* Bl = bias + (size_t)l * HIDDEN;
        const __nv_bfloat16* sh = (l & 1) ? xhiB : xhiA;
        const __nv_bfloat16* sl = (l & 1) ? xloB : xloA;
        __nv_bfloat16* dh = (l & 1) ? xhiA : xhiB;
        __nv_bfloat16* dl = (l & 1) ? xloA : xloB;
        if (l == NUM_LAYERS - 1) {
            dense_mma<true><<<grid, THREADS, SMEM_ALLOC>>>(
                sh, sl, Wh, Wl, Bl, nullptr, nullptr, out);
        } else {
            dense_mma<false><<<grid, THREADS, SMEM_ALLOC>>>(
                sh, sl, Wh, Wl, Bl, dh, dl, nullptr);
        }
    }
}

// round 8
// speedup vs baseline: 2.2801x; 1.0947x over previous
#include <cuda_runtime.h>
#include <cuda_bf16.h>
#include <stdint.h>
#include <math.h>

#define HIDDEN      512
#define BATCH       16384
#define NUM_LAYERS  8
#define NUM_OUTPUTS 16

#define BM 128
#define BN 128
#define BK 32                 // k per smem tile (32 bf16 = 64B per row)
#define KTILES (HIDDEN / BK)  // 16
#define THREADS 512           // 16 warps: 4 (M) x 4 (N), warp tile 32x32
#define STAGES 3

#define ROWSTRIDE 80          // 64B data + 16B pad -> conflict-free ldmatrix
#define MAT_BYTES (128 * ROWSTRIDE)   // 10240 per matrix tile
#define BUF_BYTES (4 * MAT_BYTES)     // xhi,xlo,whi,wlo = 40960
#define OFF_BIAS  0
#define OFF_TILES 512
#define SMEM_ALLOC (OFF_TILES + STAGES * BUF_BYTES)   // 123392

#define WSCALE 4.419417382415922e-4f   // 0.01 / sqrt(512)
#define BSCALE 0.01f
#define GAIN   1.4142135623730951f
#define SLOPE  0.2f

// Device-global scratch (allocation-free): split activations + split weights
__device__ __align__(16) __nv_bfloat16 g_xhiA[BATCH * HIDDEN];
__device__ __align__(16) __nv_bfloat16 g_xloA[BATCH * HIDDEN];
__device__ __align__(16) __nv_bfloat16 g_xhiB[BATCH * HIDDEN];
__device__ __align__(16) __nv_bfloat16 g_xloB[BATCH * HIDDEN];
__device__ __align__(16) __nv_bfloat16 g_whi[NUM_LAYERS * HIDDEN * HIDDEN];
__device__ __align__(16) __nv_bfloat16 g_wlo[NUM_LAYERS * HIDDEN * HIDDEN];

// ---------------------------------------------------------------------------
__device__ __forceinline__ uint32_t smem_u32(const void* p) {
    uint32_t a;
    asm("{ .reg .u64 t; cvta.to.shared.u64 t, %1; cvt.u32.u64 %0, t; }"
        : "=r"(a) : "l"(p));
    return a;
}
__device__ __forceinline__ float bf_round(float x) {
    return __bfloat162float(__float2bfloat16_rn(x));
}
__device__ __forceinline__ uint32_t pack_bf2(float a, float b) {
    uint32_t r;
    asm("cvt.rn.bf16x2.f32 %0, %1, %2;" : "=r"(r) : "f"(b), "f"(a));
    return r;
}
__device__ __forceinline__ float lrelu_gain(float t) {
    return (t > 0.f ? t : SLOPE * t) * GAIN;
}

#define CP_ASYNC16(dst, src) \
    asm volatile("cp.async.cg.shared.global [%0], [%1], 16;" :: "r"(dst), "l"(src))
#define CP_COMMIT() asm volatile("cp.async.commit_group;" ::: "memory")
#define CP_WAITG(n) asm volatile("cp.async.wait_group %0;" :: "n"(n) : "memory")

#define LDSM_X4(r0, r1, r2, r3, addr) \
    asm volatile("ldmatrix.sync.aligned.m8n8.x4.shared.b16 {%0,%1,%2,%3}, [%4];" \
                 : "=r"(r0), "=r"(r1), "=r"(r2), "=r"(r3) : "r"(addr))

#define MMA16816(c, a, b0, b1) \
    asm volatile("mma.sync.aligned.m16n8k16.row.col.f32.bf16.bf16.f32 " \
                 "{%0,%1,%2,%3}, {%4,%5,%6,%7}, {%8,%9}, {%0,%1,%2,%3};" \
                 : "+f"((c)[0]), "+f"((c)[1]), "+f"((c)[2]), "+f"((c)[3]) \
                 : "r"((a)[0]), "r"((a)[1]), "r"((a)[2]), "r"((a)[3]), \
                   "r"(b0), "r"(b1))

// ---------------------------------------------------------------------------
// Pre-split all layer weights: whi/wlo = split(W * wscale)
// ---------------------------------------------------------------------------
__global__ void split_w_kernel(const float* __restrict__ W,
                               __nv_bfloat16* __restrict__ whi,
                               __nv_bfloat16* __restrict__ wlo) {
    int base = (blockIdx.x * blockDim.x + threadIdx.x) * 4;
    float4 w = *reinterpret_cast<const float4*>(W + base);
    w.x *= WSCALE; w.y *= WSCALE; w.z *= WSCALE; w.w *= WSCALE;
    float h0 = bf_round(w.x), h1 = bf_round(w.y);
    float h2 = bf_round(w.z), h3 = bf_round(w.w);
    uint2 hi = make_uint2(pack_bf2(h0, h1), pack_bf2(h2, h3));
    uint2 lo = make_uint2(pack_bf2(w.x - h0, w.y - h1),
                          pack_bf2(w.z - h2, w.w - h3));
    *reinterpret_cast<uint2*>(&whi[base]) = hi;
    *reinterpret_cast<uint2*>(&wlo[base]) = lo;
}

// ---------------------------------------------------------------------------
// Pixel norm, writing split bf16 activations
// ---------------------------------------------------------------------------
__global__ void pixelnorm_split_kernel(const float* __restrict__ z,
                                       __nv_bfloat16* __restrict__ xhi,
                                       __nv_bfloat16* __restrict__ xlo) {
    int row  = blockIdx.x * blockDim.y + threadIdx.y;
    int lane = threadIdx.x;
    const float4* zr = reinterpret_cast<const float4*>(z + (size_t)row * HIDDEN);
    float4 v[4];
    float ss = 0.f;
#pragma unroll
    for (int i = 0; i < 4; i++) {
        v[i] = zr[lane + 32 * i];
        ss += v[i].x * v[i].x + v[i].y * v[i].y + v[i].z * v[i].z + v[i].w * v[i].w;
    }
#pragma unroll
    for (int off = 16; off > 0; off >>= 1)
        ss += __shfl_xor_sync(0xFFFFFFFFu, ss, off);
    float s = rsqrtf(ss * (1.0f / HIDDEN) + 1e-8f);
#pragma unroll
    for (int i = 0; i < 4; i++) {
        float x0 = v[i].x * s, x1 = v[i].y * s, x2 = v[i].z * s, x3 = v[i].w * s;
        float h0 = bf_round(x0), h1 = bf_round(x1);
        float h2 = bf_round(x2), h3 = bf_round(x3);
        int e = row * HIDDEN + (lane + 32 * i) * 4;
        *reinterpret_cast<uint2*>(&xhi[e]) =
            make_uint2(pack_bf2(h0, h1), pack_bf2(h2, h3));
        *reinterpret_cast<uint2*>(&xlo[e]) =
            make_uint2(pack_bf2(x0 - h0, x1 - h1), pack_bf2(x2 - h2, x3 - h3));
    }
}

// ---------------------------------------------------------------------------
// HMMA dense layer: acc = Xhi*Whi + Xhi*Wlo + Xlo*Whi (fp32 accum)
// 512 threads = 16 warps (4 M x 4 N); warp tile 32x32; 3-stage cp.async.
// ---------------------------------------------------------------------------
template <bool BROADCAST>
__global__ __launch_bounds__(THREADS, 1)
void dense_mma(const __nv_bfloat16* __restrict__ Xhi,
               const __nv_bfloat16* __restrict__ Xlo,
               const __nv_bfloat16* __restrict__ Whi,
               const __nv_bfloat16* __restrict__ Wlo,
               const float* __restrict__ Bv,
               __nv_bfloat16* __restrict__ Yhi,
               __nv_bfloat16* __restrict__ Ylo,
               float* __restrict__ Yout) {
    extern __shared__ char smem[];
    const uint32_t sbase = smem_u32(smem);
    float* bias_s = reinterpret_cast<float*>(smem + OFF_BIAS);

    const int tid  = threadIdx.x;
    const int wid  = tid >> 5;
    const int lane = tid & 31;
    const int mBase = blockIdx.y * BM;
    const int nBase = blockIdx.x * BN;
    const int wmBase = (wid & 3) * 32;   // warp M offset
    const int wnBase = (wid >> 2) * 32;  // warp N offset

    if (tid < BN) bias_s[tid] = Bv[nBase + tid] * BSCALE;

    const __nv_bfloat16* srcs[4] = {Xhi, Xlo, Whi, Wlo};

    // one 16B chunk per matrix per thread per stage (512 chunks/matrix)
    auto load_tile = [&](int kt, int buf) {
        uint32_t base = sbase + OFF_TILES + buf * BUF_BYTES;
        int row = tid >> 2;          // 0..127
        int c   = tid & 3;           // 16B chunk within 64B row
        uint32_t soff = (uint32_t)(row * ROWSTRIDE + c * 16);
#pragma unroll
        for (int m = 0; m < 4; m++) {
            int rowG = (m < 2 ? mBase : nBase) + row;
            const __nv_bfloat16* src =
                srcs[m] + (size_t)rowG * HIDDEN + kt * BK + c * 8;
            CP_ASYNC16(base + m * MAT_BYTES + soff, src);
        }
    };

    float c[2][4][4];
#pragma unroll
    for (int mi = 0; mi < 2; mi++)
#pragma unroll
        for (int ni = 0; ni < 4; ni++)
#pragma unroll
            for (int j = 0; j < 4; j++) c[mi][ni][j] = 0.f;

    load_tile(0, 0); CP_COMMIT();
    load_tile(1, 1); CP_COMMIT();

    for (int kt = 0; kt < KTILES; kt++) {
        const int buf = kt % STAGES;
        if (kt + 2 < KTILES) {
            load_tile(kt + 2, (kt + 2) % STAGES);
            CP_COMMIT();
            CP_WAITG(2);
        } else if (kt + 1 < KTILES) {
            CP_WAITG(1);
        } else {
            CP_WAITG(0);
        }
        __syncthreads();

        const uint32_t xb    = sbase + OFF_TILES + buf * BUF_BYTES;
        const uint32_t xhi_b = xb;
        const uint32_t xlo_b = xb + MAT_BYTES;
        const uint32_t whi_b = xb + 2 * MAT_BYTES;
        const uint32_t wlo_b = xb + 3 * MAT_BYTES;

#pragma unroll
        for (int s = 0; s < 2; s++) {          // two k16 steps per tile
            uint32_t a_hi[2][4], a_lo[2][4];
            {
                int arow  = wmBase + (lane & 15);
                int achnk = 2 * s + (lane >> 4);
                uint32_t aoff = (uint32_t)(arow * ROWSTRIDE + achnk * 16);
#pragma unroll
                for (int mi = 0; mi < 2; mi++) {
                    uint32_t ad = aoff + mi * 16 * ROWSTRIDE;
                    LDSM_X4(a_hi[mi][0], a_hi[mi][1], a_hi[mi][2], a_hi[mi][3],
                            xhi_b + ad);
                    LDSM_X4(a_lo[mi][0], a_lo[mi][1], a_lo[mi][2], a_lo[mi][3],
                            xlo_b + ad);
                }
            }
            uint32_t b_hi[4][2], b_lo[4][2];
            {
                int g = lane >> 3, r = lane & 7;
                int brow  = wnBase + (g >> 1) * 8 + r;
                int bchnk = 2 * s + (g & 1);
#pragma unroll
                for (int p = 0; p < 2; p++) {
                    uint32_t boff = (uint32_t)((brow + p * 16) * ROWSTRIDE + bchnk * 16);
                    LDSM_X4(b_hi[2 * p][0], b_hi[2 * p][1],
                            b_hi[2 * p + 1][0], b_hi[2 * p + 1][1], whi_b + boff);
                    LDSM_X4(b_lo[2 * p][0], b_lo[2 * p][1],
                            b_lo[2 * p + 1][0], b_lo[2 * p + 1][1], wlo_b + boff);
                }
            }
#pragma unroll
            for (int mi = 0; mi < 2; mi++)
#pragma unroll
                for (int ni = 0; ni < 4; ni++) {
                    MMA16816(c[mi][ni], a_hi[mi], b_hi[ni][0], b_hi[ni][1]);
                    MMA16816(c[mi][ni], a_hi[mi], b_lo[ni][0], b_lo[ni][1]);
                    MMA16816(c[mi][ni], a_lo[mi], b_hi[ni][0], b_hi[ni][1]);
                }
        }
        __syncthreads();
    }

    // ---- epilogue ----
#pragma unroll
    for (int mi = 0; mi < 2; mi++) {
        int m0 = mBase + wmBase + mi * 16 + (lane >> 2);
#pragma unroll
        for (int ni = 0; ni < 4; ni++) {
            int n = nBase + wnBase + ni * 8 + (lane & 3) * 2;
            float v0 = lrelu_gain(c[mi][ni][0] + bias_s[n - nBase]);
            float v1 = lrelu_gain(c[mi][ni][1] + bias_s[n - nBase + 1]);
            float v2 = lrelu_gain(c[mi][ni][2] + bias_s[n - nBase]);
            float v3 = lrelu_gain(c[mi][ni][3] + bias_s[n - nBase + 1]);
            if (BROADCAST) {
                float2 p01 = make_float2(v0, v1);
                float2 p23 = make_float2(v2, v3);
                float* r0 = Yout + (size_t)m0 * NUM_OUTPUTS * HIDDEN + n;
                float* r1 = r0 + (size_t)8 * NUM_OUTPUTS * HIDDEN;
#pragma unroll
                for (int rep = 0; rep < NUM_OUTPUTS; rep++) {
                    *reinterpret_cast<float2*>(r0 + rep * HIDDEN) = p01;
                    *reinterpret_cast<float2*>(r1 + rep * HIDDEN) = p23;
                }
            } else {
                float h0 = bf_round(v0), h1 = bf_round(v1);
                float h2 = bf_round(v2), h3 = bf_round(v3);
                size_t e0 = (size_t)m0 * HIDDEN + n;
                size_t e1 = e0 + (size_t)8 * HIDDEN;
                *reinterpret_cast<uint32_t*>(&Yhi[e0]) = pack_bf2(h0, h1);
                *reinterpret_cast<uint32_t*>(&Ylo[e0]) = pack_bf2(v0 - h0, v1 - h1);
                *reinterpret_cast<uint32_t*>(&Yhi[e1]) = pack_bf2(h2, h3);
                *reinterpret_cast<uint32_t*>(&Ylo[e1]) = pack_bf2(v2 - h2, v3 - h3);
            }
        }
    }
}

// ---------------------------------------------------------------------------
extern "C" void kernel_launch(void* const* d_in, const int* in_sizes, int n_in,
                              void* d_out, int out_size) {
    const float* z      = (const float*)d_in[0];
    const float* weight = (const float*)d_in[1];
    const float* bias   = (const float*)d_in[2];
    float* out          = (float*)d_out;

    __nv_bfloat16 *xhiA, *xloA, *xhiB, *xloB, *whi, *wlo;
    cudaGetSymbolAddress((void**)&xhiA, g_xhiA);
    cudaGetSymbolAddress((void**)&xloA, g_xloA);
    cudaGetSymbolAddress((void**)&xhiB, g_xhiB);
    cudaGetSymbolAddress((void**)&xloB, g_xloB);
    cudaGetSymbolAddress((void**)&whi, g_whi);
    cudaGetSymbolAddress((void**)&wlo, g_wlo);

    cudaFuncSetAttribute(dense_mma<false>,
                         cudaFuncAttributeMaxDynamicSharedMemorySize, SMEM_ALLOC);
    cudaFuncSetAttribute(dense_mma<true>,
                         cudaFuncAttributeMaxDynamicSharedMemorySize, SMEM_ALLOC);

    // 1) split all weights (wscale folded)
    split_w_kernel<<<NUM_LAYERS * HIDDEN * HIDDEN / (256 * 4), 256>>>(weight, whi, wlo);

    // 2) pixel norm -> split activations (buffer A)
    pixelnorm_split_kernel<<<BATCH / 8, dim3(32, 8)>>>(z, xhiA, xloA);

    // 3) 8 HMMA dense layers, ping-pong; last broadcasts into wp
    dim3 grid(HIDDEN / BN, BATCH / BM);  // (4, 128)
    for (int l = 0; l < NUM_LAYERS; l++) {
        const __nv_bfloat16* Wh = whi + (size_t)l * HIDDEN * HIDDEN;
        const __nv_bfloat16* Wl = wlo + (size_t)l * HIDDEN * HIDDEN;
        const float* Bl = bias + (size_t)l * HIDDEN;
        const __nv_bfloat16* sh = (l & 1) ? xhiB : xhiA;
        const __nv_bfloat16* sl = (l & 1) ? xloB : xloA;
        __nv_bfloat16* dh = (l & 1) ? xhiA : xhiB;
        __nv_bfloat16* dl = (l & 1) ? xloA : xloB;
        if (l == NUM_LAYERS - 1) {
            dense_mma<true><<<grid, THREADS, SMEM_ALLOC>>>(
                sh, sl, Wh, Wl, Bl, nullptr, nullptr, out);
        } else {
            dense_mma<false><<<grid, THREADS, SMEM_ALLOC>>>(
                sh, sl, Wh, Wl, Bl, dh, dl, nullptr);
        }
    }
}

// round 10
// speedup vs baseline: 2.3304x; 1.0221x over previous
#include <cuda_runtime.h>
#include <cuda_bf16.h>
#include <stdint.h>
#include <math.h>

#define HIDDEN      512
#define BATCH       16384
#define NUM_LAYERS  8
#define NUM_OUTPUTS 16

#define BM 128
#define BN 128
#define BK 64                 // k per smem tile (64 bf16 = 128B per row)
#define KTILES (HIDDEN / BK)  // 8
#define THREADS 512           // 16 warps: 4 (M) x 4 (N), warp tile 32x32
#define STAGES 2

#define ROWSTRIDE 144         // 128B data + 16B pad (stride 9 chunks mod 32 banks)
#define MAT_BYTES (128 * ROWSTRIDE)   // 18432 per matrix tile
#define BUF_BYTES (4 * MAT_BYTES)     // xhi,xlo,whi,wlo = 73728
#define OFF_BIAS  0
#define OFF_TILES 512
#define SMEM_ALLOC (OFF_TILES + STAGES * BUF_BYTES)   // 147968

#define WSCALE 4.419417382415922e-4f   // 0.01 / sqrt(512)
#define BSCALE 0.01f
#define GAIN   1.4142135623730951f
#define SLOPE  0.2f

// Device-global scratch (allocation-free): split activations + split weights
__device__ __align__(16) __nv_bfloat16 g_xhiA[BATCH * HIDDEN];
__device__ __align__(16) __nv_bfloat16 g_xloA[BATCH * HIDDEN];
__device__ __align__(16) __nv_bfloat16 g_xhiB[BATCH * HIDDEN];
__device__ __align__(16) __nv_bfloat16 g_xloB[BATCH * HIDDEN];
__device__ __align__(16) __nv_bfloat16 g_whi[NUM_LAYERS * HIDDEN * HIDDEN];
__device__ __align__(16) __nv_bfloat16 g_wlo[NUM_LAYERS * HIDDEN * HIDDEN];

// ---------------------------------------------------------------------------
__device__ __forceinline__ uint32_t smem_u32(const void* p) {
    uint32_t a;
    asm("{ .reg .u64 t; cvta.to.shared.u64 t, %1; cvt.u32.u64 %0, t; }"
        : "=r"(a) : "l"(p));
    return a;
}
__device__ __forceinline__ float bf_round(float x) {
    return __bfloat162float(__float2bfloat16_rn(x));
}
__device__ __forceinline__ uint32_t pack_bf2(float a, float b) {
    uint32_t r;
    asm("cvt.rn.bf16x2.f32 %0, %1, %2;" : "=r"(r) : "f"(b), "f"(a));
    return r;
}
__device__ __forceinline__ float lrelu_gain(float t) {
    return (t > 0.f ? t : SLOPE * t) * GAIN;
}

#define CP_ASYNC16(dst, src) \
    asm volatile("cp.async.cg.shared.global [%0], [%1], 16;" :: "r"(dst), "l"(src))
#define CP_COMMIT() asm volatile("cp.async.commit_group;" ::: "memory")
#define CP_WAITG(n) asm volatile("cp.async.wait_group %0;" :: "n"(n) : "memory")

#define LDSM_X4(r0, r1, r2, r3, addr) \
    asm volatile("ldmatrix.sync.aligned.m8n8.x4.shared.b16 {%0,%1,%2,%3}, [%4];" \
                 : "=r"(r0), "=r"(r1), "=r"(r2), "=r"(r3) : "r"(addr))

#define MMA16816(c, a, b0, b1) \
    asm volatile("mma.sync.aligned.m16n8k16.row.col.f32.bf16.bf16.f32 " \
                 "{%0,%1,%2,%3}, {%4,%5,%6,%7}, {%8,%9}, {%0,%1,%2,%3};" \
                 : "+f"((c)[0]), "+f"((c)[1]), "+f"((c)[2]), "+f"((c)[3]) \
                 : "r"((a)[0]), "r"((a)[1]), "r"((a)[2]), "r"((a)[3]), \
                   "r"(b0), "r"(b1))

// ---------------------------------------------------------------------------
// Pre-split all layer weights: whi/wlo = split(W * wscale)
// ---------------------------------------------------------------------------
__global__ void split_w_kernel(const float* __restrict__ W,
                               __nv_bfloat16* __restrict__ whi,
                               __nv_bfloat16* __restrict__ wlo) {
    int base = (blockIdx.x * blockDim.x + threadIdx.x) * 4;
    float4 w = *reinterpret_cast<const float4*>(W + base);
    w.x *= WSCALE; w.y *= WSCALE; w.z *= WSCALE; w.w *= WSCALE;
    float h0 = bf_round(w.x), h1 = bf_round(w.y);
    float h2 = bf_round(w.z), h3 = bf_round(w.w);
    uint2 hi = make_uint2(pack_bf2(h0, h1), pack_bf2(h2, h3));
    uint2 lo = make_uint2(pack_bf2(w.x - h0, w.y - h1),
                          pack_bf2(w.z - h2, w.w - h3));
    *reinterpret_cast<uint2*>(&whi[base]) = hi;
    *reinterpret_cast<uint2*>(&wlo[base]) = lo;
}

// ---------------------------------------------------------------------------
// Pixel norm, writing split bf16 activations
// ---------------------------------------------------------------------------
__global__ void pixelnorm_split_kernel(const float* __restrict__ z,
                                       __nv_bfloat16* __restrict__ xhi,
                                       __nv_bfloat16* __restrict__ xlo) {
    int row  = blockIdx.x * blockDim.y + threadIdx.y;
    int lane = threadIdx.x;
    const float4* zr = reinterpret_cast<const float4*>(z + (size_t)row * HIDDEN);
    float4 v[4];
    float ss = 0.f;
#pragma unroll
    for (int i = 0; i < 4; i++) {
        v[i] = zr[lane + 32 * i];
        ss += v[i].x * v[i].x + v[i].y * v[i].y + v[i].z * v[i].z + v[i].w * v[i].w;
    }
#pragma unroll
    for (int off = 16; off > 0; off >>= 1)
        ss += __shfl_xor_sync(0xFFFFFFFFu, ss, off);
    float s = rsqrtf(ss * (1.0f / HIDDEN) + 1e-8f);
#pragma unroll
    for (int i = 0; i < 4; i++) {
        float x0 = v[i].x * s, x1 = v[i].y * s, x2 = v[i].z * s, x3 = v[i].w * s;
        float h0 = bf_round(x0), h1 = bf_round(x1);
        float h2 = bf_round(x2), h3 = bf_round(x3);
        int e = row * HIDDEN + (lane + 32 * i) * 4;
        *reinterpret_cast<uint2*>(&xhi[e]) =
            make_uint2(pack_bf2(h0, h1), pack_bf2(h2, h3));
        *reinterpret_cast<uint2*>(&xlo[e]) =
            make_uint2(pack_bf2(x0 - h0, x1 - h1), pack_bf2(x2 - h2, x3 - h3));
    }
}

// ---------------------------------------------------------------------------
// HMMA dense layer: acc = Xhi*Whi + Xhi*Wlo + Xlo*Whi (fp32 accum)
// 512 threads = 16 warps (4 M x 4 N); warp tile 32x32; BK=64, 2-stage
// cp.async, ONE barrier per ktile (loads issued post-sync -> race-free).
// ---------------------------------------------------------------------------
template <bool BROADCAST>
__global__ __launch_bounds__(THREADS, 1)
void dense_mma(const __nv_bfloat16* __restrict__ Xhi,
               const __nv_bfloat16* __restrict__ Xlo,
               const __nv_bfloat16* __restrict__ Whi,
               const __nv_bfloat16* __restrict__ Wlo,
               const float* __restrict__ Bv,
               __nv_bfloat16* __restrict__ Yhi,
               __nv_bfloat16* __restrict__ Ylo,
               float* __restrict__ Yout) {
    extern __shared__ char smem[];
    const uint32_t sbase = smem_u32(smem);
    float* bias_s = reinterpret_cast<float*>(smem + OFF_BIAS);

    const int tid  = threadIdx.x;
    const int wid  = tid >> 5;
    const int lane = tid & 31;
    const int mBase = blockIdx.y * BM;
    const int nBase = blockIdx.x * BN;
    const int wmBase = (wid & 3) * 32;   // warp M offset
    const int wnBase = (wid >> 2) * 32;  // warp N offset

    if (tid < BN) bias_s[tid] = Bv[nBase + tid] * BSCALE;

    const __nv_bfloat16* srcs[4] = {Xhi, Xlo, Whi, Wlo};

    // per tile: 4 matrices x 128 rows x 8 chunks(16B); 2 chunks/matrix/thread
    auto load_tile = [&](int kt, int buf) {
        uint32_t base = sbase + OFF_TILES + buf * BUF_BYTES;
#pragma unroll
        for (int i = 0; i < 2; i++) {
            int chunk = tid + i * THREADS;     // 0..1023
            int row = chunk >> 3;              // 0..127
            int c   = chunk & 7;               // 16B chunk within 128B row
            uint32_t soff = (uint32_t)(row * ROWSTRIDE + c * 16);
#pragma unroll
            for (int m = 0; m < 4; m++) {
                int rowG = (m < 2 ? mBase : nBase) + row;
                const __nv_bfloat16* src =
                    srcs[m] + (size_t)rowG * HIDDEN + kt * BK + c * 8;
                CP_ASYNC16(base + m * MAT_BYTES + soff, src);
            }
        }
    };

    float c[2][4][4];
#pragma unroll
    for (int mi = 0; mi < 2; mi++)
#pragma unroll
        for (int ni = 0; ni < 4; ni++)
#pragma unroll
            for (int j = 0; j < 4; j++) c[mi][ni][j] = 0.f;

    load_tile(0, 0); CP_COMMIT();

    for (int kt = 0; kt < KTILES; kt++) {
        const int buf = kt & 1;
        CP_WAITG(0);            // tile kt resident
        __syncthreads();        // all warps past reads of buf (kt-1)&1

        if (kt + 1 < KTILES) {  // prefetch overlaps compute; post-sync = safe
            load_tile(kt + 1, buf ^ 1);
            CP_COMMIT();
        }

        const uint32_t xb    = sbase + OFF_TILES + buf * BUF_BYTES;
        const uint32_t xhi_b = xb;
        const uint32_t xlo_b = xb + MAT_BYTES;
        const uint32_t whi_b = xb + 2 * MAT_BYTES;
        const uint32_t wlo_b = xb + 3 * MAT_BYTES;

#pragma unroll
        for (int s = 0; s < 4; s++) {          // four k16 steps per tile
            uint32_t a_hi[2][4], a_lo[2][4];
            {
                int arow  = wmBase + (lane & 15);
                int achnk = 2 * s + (lane >> 4);
                uint32_t aoff = (uint32_t)(arow * ROWSTRIDE + achnk * 16);
#pragma unroll
                for (int mi = 0; mi < 2; mi++) {
                    uint32_t ad = aoff + mi * 16 * ROWSTRIDE;
                    LDSM_X4(a_hi[mi][0], a_hi[mi][1], a_hi[mi][2], a_hi[mi][3],
                            xhi_b + ad);
                    LDSM_X4(a_lo[mi][0], a_lo[mi][1], a_lo[mi][2], a_lo[mi][3],
                            xlo_b + ad);
                }
            }
            uint32_t b_hi[4][2], b_lo[4][2];
            {
                int g = lane >> 3, r = lane & 7;
                int brow  = wnBase + (g >> 1) * 8 + r;
                int bchnk = 2 * s + (g & 1);
#pragma unroll
                for (int p = 0; p < 2; p++) {
                    uint32_t boff = (uint32_t)((brow + p * 16) * ROWSTRIDE + bchnk * 16);
                    LDSM_X4(b_hi[2 * p][0], b_hi[2 * p][1],
                            b_hi[2 * p + 1][0], b_hi[2 * p + 1][1], whi_b + boff);
                    LDSM_X4(b_lo[2 * p][0], b_lo[2 * p][1],
                            b_lo[2 * p + 1][0], b_lo[2 * p + 1][1], wlo_b + boff);
                }
            }
#pragma unroll
            for (int mi = 0; mi < 2; mi++)
#pragma unroll
                for (int ni = 0; ni < 4; ni++) {
                    MMA16816(c[mi][ni], a_hi[mi], b_hi[ni][0], b_hi[ni][1]);
                    MMA16816(c[mi][ni], a_hi[mi], b_lo[ni][0], b_lo[ni][1]);
                    MMA16816(c[mi][ni], a_lo[mi], b_hi[ni][0], b_hi[ni][1]);
                }
        }
    }

    // ---- epilogue ----
    if (BROADCAST) {
        // stage fp32 tile in smem (reuse tile buffers), then coalesced float4
        __syncthreads();   // all LDSM reads done; tile region free
        float* stage = reinterpret_cast<float*>(smem + OFF_TILES);
        const int LDSTG = 132;   // padded fp32 row stride
#pragma unroll
        for (int mi = 0; mi < 2; mi++) {
            int r0 = wmBase + mi * 16 + (lane >> 2);
#pragma unroll
            for (int ni = 0; ni < 4; ni++) {
                int n = wnBase + ni * 8 + (lane & 3) * 2;
                stage[r0 * LDSTG + n]           = lrelu_gain(c[mi][ni][0] + bias_s[n]);
                stage[r0 * LDSTG + n + 1]       = lrelu_gain(c[mi][ni][1] + bias_s[n + 1]);
                stage[(r0 + 8) * LDSTG + n]     = lrelu_gain(c[mi][ni][2] + bias_s[n]);
                stage[(r0 + 8) * LDSTG + n + 1] = lrelu_gain(c[mi][ni][3] + bias_s[n + 1]);
            }
        }
        __syncthreads();
        // 128 rows x 16 reps x 32 float4-cols, 512 threads -> 128 iters
        for (int it = tid; it < 128 * NUM_OUTPUTS * 32; it += THREADS) {
            int col4 = it & 31;
            int rep  = (it >> 5) & 15;
            int row  = it >> 9;
            float4 v = *reinterpret_cast<const float4*>(
                &stage[row * LDSTG + col4 * 4]);
            *reinterpret_cast<float4*>(
                Yout + ((size_t)(mBase + row) * NUM_OUTPUTS + rep) * HIDDEN
                     + nBase + col4 * 4) = v;
        }
    } else {
#pragma unroll
        for (int mi = 0; mi < 2; mi++) {
            int m0 = mBase + wmBase + mi * 16 + (lane >> 2);
#pragma unroll
            for (int ni = 0; ni < 4; ni++) {
                int n = nBase + wnBase + ni * 8 + (lane & 3) * 2;
                float v0 = lrelu_gain(c[mi][ni][0] + bias_s[n - nBase]);
                float v1 = lrelu_gain(c[mi][ni][1] + bias_s[n - nBase + 1]);
                float v2 = lrelu_gain(c[mi][ni][2] + bias_s[n - nBase]);
                float v3 = lrelu_gain(c[mi][ni][3] + bias_s[n - nBase + 1]);
                float h0 = bf_round(v0), h1 = bf_round(v1);
                float h2 = bf_round(v2), h3 = bf_round(v3);
                size_t e0 = (size_t)m0 * HIDDEN + n;
                size_t e1 = e0 + (size_t)8 * HIDDEN;
                *reinterpret_cast<uint32_t*>(&Yhi[e0]) = pack_bf2(h0, h1);
                *reinterpret_cast<uint32_t*>(&Ylo[e0]) = pack_bf2(v0 - h0, v1 - h1);
                *reinterpret_cast<uint32_t*>(&Yhi[e1]) = pack_bf2(h2, h3);
                *reinterpret_cast<uint32_t*>(&Ylo[e1]) = pack_bf2(v2 - h2, v3 - h3);
            }
        }
    }
}

// ---------------------------------------------------------------------------
extern "C" void kernel_launch(void* const* d_in, const int* in_sizes, int n_in,
                              void* d_out, int out_size) {
    const float* z      = (const float*)d_in[0];
    const float* weight = (const float*)d_in[1];
    const float* bias   = (const float*)d_in[2];
    float* out          = (float*)d_out;

    __nv_bfloat16 *xhiA, *xloA, *xhiB, *xloB, *whi, *wlo;
    cudaGetSymbolAddress((void**)&xhiA, g_xhiA);
    cudaGetSymbolAddress((void**)&xloA, g_xloA);
    cudaGetSymbolAddress((void**)&xhiB, g_xhiB);
    cudaGetSymbolAddress((void**)&xloB, g_xloB);
    cudaGetSymbolAddress((void**)&whi, g_whi);
    cudaGetSymbolAddress((void**)&wlo, g_wlo);

    cudaFuncSetAttribute(dense_mma<false>,
                         cudaFuncAttributeMaxDynamicSharedMemorySize, SMEM_ALLOC);
    cudaFuncSetAttribute(dense_mma<true>,
                         cudaFuncAttributeMaxDynamicSharedMemorySize, SMEM_ALLOC);

    // 1) split all weights (wscale folded)
    split_w_kernel<<<NUM_LAYERS * HIDDEN * HIDDEN / (256 * 4), 256>>>(weight, whi, wlo);

    // 2) pixel norm -> split activations (buffer A)
    pixelnorm_split_kernel<<<BATCH / 8, dim3(32, 8)>>>(z, xhiA, xloA);

    // 3) 8 HMMA dense layers, ping-pong; last broadcasts into wp
    dim3 grid(HIDDEN / BN, BATCH / BM);  // (4, 128)
    for (int l = 0; l < NUM_LAYERS; l++) {
        const __nv_bfloat16* Wh = whi + (size_t)l * HIDDEN * HIDDEN;
        const __nv_bfloat16* Wl = wlo + (size_t)l * HIDDEN * HIDDEN;
        const float* Bl = bias + (size_t)l * HIDDEN;
        const __nv_bfloat16* sh = (l & 1) ? xhiB : xhiA;
        const __nv_bfloat16* sl = (l & 1) ? xloB : xloA;
        __nv_bfloat16* dh = (l & 1) ? xhiA : xhiB;
        __nv_bfloat16* dl = (l & 1) ? xloA : xloB;
        if (l == NUM_LAYERS - 1) {
            dense_mma<true><<<grid, THREADS, SMEM_ALLOC>>>(
                sh, sl, Wh, Wl, Bl, nullptr, nullptr, out);
        } else {
            dense_mma<false><<<grid, THREADS, SMEM_ALLOC>>>(
                sh, sl, Wh, Wl, Bl, dh, dl, nullptr);
        }
    }
}

// round 11
// speedup vs baseline: 2.3938x; 1.0272x over previous
#include <cuda_runtime.h>
#include <cuda_bf16.h>
#include <stdint.h>
#include <math.h>

#define HIDDEN      512
#define BATCH       16384
#define NUM_LAYERS  8
#define NUM_OUTPUTS 16

#define BM 128
#define BN 128
#define BK 32                 // k per smem tile (32 bf16 = 64B per row)
#define KTILES (HIDDEN / BK)  // 16
#define THREADS 512           // 16 warps: 4 (M) x 4 (N), warp tile 32x32
#define STAGES 3

#define ROWSTRIDE 80          // 64B data + 16B pad -> conflict-free ldmatrix
#define MAT_BYTES (128 * ROWSTRIDE)   // 10240 per matrix tile
#define BUF_BYTES (4 * MAT_BYTES)     // xhi,xlo,whi,wlo = 40960
#define OFF_BIAS  0
#define OFF_TILES 512
#define SMEM_ALLOC (OFF_TILES + STAGES * BUF_BYTES)   // 123392

#define WSCALE 4.419417382415922e-4f   // 0.01 / sqrt(512)
#define BSCALE 0.01f
#define GAIN   1.4142135623730951f
#define SLOPE  0.2f

// Device-global scratch (allocation-free): split activations + split weights
__device__ __align__(16) __nv_bfloat16 g_xhiA[BATCH * HIDDEN];
__device__ __align__(16) __nv_bfloat16 g_xloA[BATCH * HIDDEN];
__device__ __align__(16) __nv_bfloat16 g_xhiB[BATCH * HIDDEN];
__device__ __align__(16) __nv_bfloat16 g_xloB[BATCH * HIDDEN];
__device__ __align__(16) __nv_bfloat16 g_whi[NUM_LAYERS * HIDDEN * HIDDEN];
__device__ __align__(16) __nv_bfloat16 g_wlo[NUM_LAYERS * HIDDEN * HIDDEN];

// ---------------------------------------------------------------------------
__device__ __forceinline__ uint32_t smem_u32(const void* p) {
    uint32_t a;
    asm("{ .reg .u64 t; cvta.to.shared.u64 t, %1; cvt.u32.u64 %0, t; }"
        : "=r"(a) : "l"(p));
    return a;
}
__device__ __forceinline__ float bf_round(float x) {
    return __bfloat162float(__float2bfloat16_rn(x));
}
__device__ __forceinline__ uint32_t pack_bf2(float a, float b) {
    uint32_t r;
    asm("cvt.rn.bf16x2.f32 %0, %1, %2;" : "=r"(r) : "f"(b), "f"(a));
    return r;
}
__device__ __forceinline__ float lrelu_gain(float t) {
    return (t > 0.f ? t : SLOPE * t) * GAIN;
}

#define CP_ASYNC16(dst, src) \
    asm volatile("cp.async.cg.shared.global [%0], [%1], 16;" :: "r"(dst), "l"(src))
#define CP_COMMIT() asm volatile("cp.async.commit_group;" ::: "memory")
#define CP_WAITG(n) asm volatile("cp.async.wait_group %0;" :: "n"(n) : "memory")

#define LDSM_X4(r0, r1, r2, r3, addr) \
    asm volatile("ldmatrix.sync.aligned.m8n8.x4.shared.b16 {%0,%1,%2,%3}, [%4];" \
                 : "=r"(r0), "=r"(r1), "=r"(r2), "=r"(r3) : "r"(addr))

#define MMA16816(c, a, b0, b1) \
    asm volatile("mma.sync.aligned.m16n8k16.row.col.f32.bf16.bf16.f32 " \
                 "{%0,%1,%2,%3}, {%4,%5,%6,%7}, {%8,%9}, {%0,%1,%2,%3};" \
                 : "+f"((c)[0]), "+f"((c)[1]), "+f"((c)[2]), "+f"((c)[3]) \
                 : "r"((a)[0]), "r"((a)[1]), "r"((a)[2]), "r"((a)[3]), \
                   "r"(b0), "r"(b1))

// ---------------------------------------------------------------------------
// Pre-split all layer weights: whi/wlo = split(W * wscale)
// ---------------------------------------------------------------------------
__global__ void split_w_kernel(const float* __restrict__ W,
                               __nv_bfloat16* __restrict__ whi,
                               __nv_bfloat16* __restrict__ wlo) {
    int base = (blockIdx.x * blockDim.x + threadIdx.x) * 4;
    float4 w = *reinterpret_cast<const float4*>(W + base);
    w.x *= WSCALE; w.y *= WSCALE; w.z *= WSCALE; w.w *= WSCALE;
    float h0 = bf_round(w.x), h1 = bf_round(w.y);
    float h2 = bf_round(w.z), h3 = bf_round(w.w);
    uint2 hi = make_uint2(pack_bf2(h0, h1), pack_bf2(h2, h3));
    uint2 lo = make_uint2(pack_bf2(w.x - h0, w.y - h1),
                          pack_bf2(w.z - h2, w.w - h3));
    *reinterpret_cast<uint2*>(&whi[base]) = hi;
    *reinterpret_cast<uint2*>(&wlo[base]) = lo;
}

// ---------------------------------------------------------------------------
// Pixel norm, writing split bf16 activations
// ---------------------------------------------------------------------------
__global__ void pixelnorm_split_kernel(const float* __restrict__ z,
                                       __nv_bfloat16* __restrict__ xhi,
                                       __nv_bfloat16* __restrict__ xlo) {
    int row  = blockIdx.x * blockDim.y + threadIdx.y;
    int lane = threadIdx.x;
    const float4* zr = reinterpret_cast<const float4*>(z + (size_t)row * HIDDEN);
    float4 v[4];
    float ss = 0.f;
#pragma unroll
    for (int i = 0; i < 4; i++) {
        v[i] = zr[lane + 32 * i];
        ss += v[i].x * v[i].x + v[i].y * v[i].y + v[i].z * v[i].z + v[i].w * v[i].w;
    }
#pragma unroll
    for (int off = 16; off > 0; off >>= 1)
        ss += __shfl_xor_sync(0xFFFFFFFFu, ss, off);
    float s = rsqrtf(ss * (1.0f / HIDDEN) + 1e-8f);
#pragma unroll
    for (int i = 0; i < 4; i++) {
        float x0 = v[i].x * s, x1 = v[i].y * s, x2 = v[i].z * s, x3 = v[i].w * s;
        float h0 = bf_round(x0), h1 = bf_round(x1);
        float h2 = bf_round(x2), h3 = bf_round(x3);
        int e = row * HIDDEN + (lane + 32 * i) * 4;
        *reinterpret_cast<uint2*>(&xhi[e]) =
            make_uint2(pack_bf2(h0, h1), pack_bf2(h2, h3));
        *reinterpret_cast<uint2*>(&xlo[e]) =
            make_uint2(pack_bf2(x0 - h0, x1 - h1), pack_bf2(x2 - h2, x3 - h3));
    }
}

// ---------------------------------------------------------------------------
// HMMA dense layer: acc = Xhi*Whi + Xhi*Wlo + Xlo*Whi (fp32 accum)
// 16 warps (4Mx4N), warp tile 32x32, BK=32, 3-stage cp.async smem ring,
// double-buffered register fragments (LDSM for next step overlaps MMAs).
// ---------------------------------------------------------------------------
template <bool BROADCAST>
__global__ __launch_bounds__(THREADS, 1)
void dense_mma(const __nv_bfloat16* __restrict__ Xhi,
               const __nv_bfloat16* __restrict__ Xlo,
               const __nv_bfloat16* __restrict__ Whi,
               const __nv_bfloat16* __restrict__ Wlo,
               const float* __restrict__ Bv,
               __nv_bfloat16* __restrict__ Yhi,
               __nv_bfloat16* __restrict__ Ylo,
               float* __restrict__ Yout) {
    extern __shared__ char smem[];
    const uint32_t sbase = smem_u32(smem);
    float* bias_s = reinterpret_cast<float*>(smem + OFF_BIAS);

    const int tid  = threadIdx.x;
    const int wid  = tid >> 5;
    const int lane = tid & 31;
    const int mBase = blockIdx.y * BM;
    const int nBase = blockIdx.x * BN;
    const int wmBase = (wid & 3) * 32;   // warp M offset
    const int wnBase = (wid >> 2) * 32;  // warp N offset

    if (tid < BN) bias_s[tid] = Bv[nBase + tid] * BSCALE;

    const __nv_bfloat16* srcs[4] = {Xhi, Xlo, Whi, Wlo};

    // one 16B chunk per matrix per thread per stage (512 chunks/matrix)
    auto load_tile = [&](int kt, int buf) {
        uint32_t base = sbase + OFF_TILES + buf * BUF_BYTES;
        int row = tid >> 2;          // 0..127
        int c   = tid & 3;           // 16B chunk within 64B row
        uint32_t soff = (uint32_t)(row * ROWSTRIDE + c * 16);
#pragma unroll
        for (int m = 0; m < 4; m++) {
            int rowG = (m < 2 ? mBase : nBase) + row;
            const __nv_bfloat16* src =
                srcs[m] + (size_t)rowG * HIDDEN + kt * BK + c * 8;
            CP_ASYNC16(base + m * MAT_BYTES + soff, src);
        }
    };

    // per-warp ldsm address components (constant across steps)
    const uint32_t a_off0 =
        (uint32_t)((wmBase + (lane & 15)) * ROWSTRIDE + (lane >> 4) * 16);
    const int bg = lane >> 3, br = lane & 7;
    const uint32_t b_off0 =
        (uint32_t)((wnBase + (bg >> 1) * 8 + br) * ROWSTRIDE + (bg & 1) * 16);

    // frag load for step s of tile in buffer buf -> set
    auto load_frags = [&](int buf, int s,
                          uint32_t aH[2][4], uint32_t aL[2][4],
                          uint32_t bH[4][2], uint32_t bL[4][2]) {
        const uint32_t xb    = sbase + OFF_TILES + buf * BUF_BYTES;
        const uint32_t xhi_b = xb;
        const uint32_t xlo_b = xb + MAT_BYTES;
        const uint32_t whi_b = xb + 2 * MAT_BYTES;
        const uint32_t wlo_b = xb + 3 * MAT_BYTES;
        const uint32_t sk = (uint32_t)(2 * s * 16);
#pragma unroll
        for (int mi = 0; mi < 2; mi++) {
            uint32_t ad = a_off0 + sk + mi * 16 * ROWSTRIDE;
            LDSM_X4(aH[mi][0], aH[mi][1], aH[mi][2], aH[mi][3], xhi_b + ad);
            LDSM_X4(aL[mi][0], aL[mi][1], aL[mi][2], aL[mi][3], xlo_b + ad);
        }
#pragma unroll
        for (int p = 0; p < 2; p++) {
            uint32_t bd = b_off0 + sk + p * 16 * ROWSTRIDE;
            LDSM_X4(bH[2 * p][0], bH[2 * p][1], bH[2 * p + 1][0],
                    bH[2 * p + 1][1], whi_b + bd);
            LDSM_X4(bL[2 * p][0], bL[2 * p][1], bL[2 * p + 1][0],
                    bL[2 * p + 1][1], wlo_b + bd);
        }
    };

    float c[2][4][4];
#pragma unroll
    for (int mi = 0; mi < 2; mi++)
#pragma unroll
        for (int ni = 0; ni < 4; ni++)
#pragma unroll
            for (int j = 0; j < 4; j++) c[mi][ni][j] = 0.f;

    auto do_mma = [&](uint32_t aH[2][4], uint32_t aL[2][4],
                      uint32_t bH[4][2], uint32_t bL[4][2]) {
#pragma unroll
        for (int mi = 0; mi < 2; mi++)
#pragma unroll
            for (int ni = 0; ni < 4; ni++) {
                MMA16816(c[mi][ni], aH[mi], bH[ni][0], bH[ni][1]);
                MMA16816(c[mi][ni], aH[mi], bL[ni][0], bL[ni][1]);
                MMA16816(c[mi][ni], aL[mi], bH[ni][0], bH[ni][1]);
            }
    };

    uint32_t aH[2][2][4], aL[2][2][4], bH[2][4][2], bL[2][4][2];

    load_tile(0, 0); CP_COMMIT();
    load_tile(1, 1); CP_COMMIT();
    CP_WAITG(1);            // tile 0 resident
    __syncthreads();
    load_frags(0, 0, aH[0], aL[0], bH[0], bL[0]);

    for (int kt = 0; kt < KTILES; kt++) {
        const int buf = kt % STAGES;

        // LDSMs for step 1 issue before MMAs of step 0 -> latency hidden
        load_frags(buf, 1, aH[1], aL[1], bH[1], bL[1]);
        do_mma(aH[0], aL[0], bH[0], bL[0]);

        if (kt + 2 < KTILES) {          // prefetch tile kt+2 (3rd buffer: free)
            load_tile(kt + 2, (kt + 2) % STAGES);
            CP_COMMIT();
        }
        if (kt + 1 < KTILES) {
            if (kt + 2 < KTILES) CP_WAITG(1); else CP_WAITG(0);  // tile kt+1 in
            __syncthreads();            // all warps done reading tile kt
            load_frags((kt + 1) % STAGES, 0, aH[0], aL[0], bH[0], bL[0]);
        }
        do_mma(aH[1], aL[1], bH[1], bL[1]);
    }

    // ---- epilogue ----
    if (BROADCAST) {
        // stage fp32 tile in smem (reuse tile buffers), then coalesced float4
        __syncthreads();
        float* stage = reinterpret_cast<float*>(smem + OFF_TILES);
        const int LDSTG = 132;   // padded fp32 row stride
#pragma unroll
        for (int mi = 0; mi < 2; mi++) {
            int r0 = wmBase + mi * 16 + (lane >> 2);
#pragma unroll
            for (int ni = 0; ni < 4; ni++) {
                int n = wnBase + ni * 8 + (lane & 3) * 2;
                stage[r0 * LDSTG + n]           = lrelu_gain(c[mi][ni][0] + bias_s[n]);
                stage[r0 * LDSTG + n + 1]       = lrelu_gain(c[mi][ni][1] + bias_s[n + 1]);
                stage[(r0 + 8) * LDSTG + n]     = lrelu_gain(c[mi][ni][2] + bias_s[n]);
                stage[(r0 + 8) * LDSTG + n + 1] = lrelu_gain(c[mi][ni][3] + bias_s[n + 1]);
            }
        }
        __syncthreads();
        // 128 rows x 16 reps x 32 float4-cols, 512 threads -> 128 iters
        for (int it = tid; it < 128 * NUM_OUTPUTS * 32; it += THREADS) {
            int col4 = it & 31;
            int rep  = (it >> 5) & 15;
            int row  = it >> 9;
            float4 v = *reinterpret_cast<const float4*>(
                &stage[row * LDSTG + col4 * 4]);
            *reinterpret_cast<float4*>(
                Yout + ((size_t)(mBase + row) * NUM_OUTPUTS + rep) * HIDDEN
                     + nBase + col4 * 4) = v;
        }
    } else {
#pragma unroll
        for (int mi = 0; mi < 2; mi++) {
            int m0 = mBase + wmBase + mi * 16 + (lane >> 2);
#pragma unroll
            for (int ni = 0; ni < 4; ni++) {
                int n = nBase + wnBase + ni * 8 + (lane & 3) * 2;
                float v0 = lrelu_gain(c[mi][ni][0] + bias_s[n - nBase]);
                float v1 = lrelu_gain(c[mi][ni][1] + bias_s[n - nBase + 1]);
                float v2 = lrelu_gain(c[mi][ni][2] + bias_s[n - nBase]);
                float v3 = lrelu_gain(c[mi][ni][3] + bias_s[n - nBase + 1]);
                float h0 = bf_round(v0), h1 = bf_round(v1);
                float h2 = bf_round(v2), h3 = bf_round(v3);
                size_t e0 = (size_t)m0 * HIDDEN + n;
                size_t e1 = e0 + (size_t)8 * HIDDEN;
                *reinterpret_cast<uint32_t*>(&Yhi[e0]) = pack_bf2(h0, h1);
                *reinterpret_cast<uint32_t*>(&Ylo[e0]) = pack_bf2(v0 - h0, v1 - h1);
                *reinterpret_cast<uint32_t*>(&Yhi[e1]) = pack_bf2(h2, h3);
                *reinterpret_cast<uint32_t*>(&Ylo[e1]) = pack_bf2(v2 - h2, v3 - h3);
            }
        }
    }
}

// ---------------------------------------------------------------------------
extern "C" void kernel_launch(void* const* d_in, const int* in_sizes, int n_in,
                              void* d_out, int out_size) {
    const float* z      = (const float*)d_in[0];
    const float* weight = (const float*)d_in[1];
    const float* bias   = (const float*)d_in[2];
    float* out          = (float*)d_out;

    __nv_bfloat16 *xhiA, *xloA, *xhiB, *xloB, *whi, *wlo;
    cudaGetSymbolAddress((void**)&xhiA, g_xhiA);
    cudaGetSymbolAddress((void**)&xloA, g_xloA);
    cudaGetSymbolAddress((void**)&xhiB, g_xhiB);
    cudaGetSymbolAddress((void**)&xloB, g_xloB);
    cudaGetSymbolAddress((void**)&whi, g_whi);
    cudaGetSymbolAddress((void**)&wlo, g_wlo);

    cudaFuncSetAttribute(dense_mma<false>,
                         cudaFuncAttributeMaxDynamicSharedMemorySize, SMEM_ALLOC);
    cudaFuncSetAttribute(dense_mma<true>,
                         cudaFuncAttributeMaxDynamicSharedMemorySize, SMEM_ALLOC);

    // 1) split all weights (wscale folded)
    split_w_kernel<<<NUM_LAYERS * HIDDEN * HIDDEN / (256 * 4), 256>>>(weight, whi, wlo);

    // 2) pixel norm -> split activations (buffer A)
    pixelnorm_split_kernel<<<BATCH / 8, dim3(32, 8)>>>(z, xhiA, xloA);

    // 3) 8 HMMA dense layers, ping-pong; last broadcasts into wp
    dim3 grid(HIDDEN / BN, BATCH / BM);  // (4, 128)
    for (int l = 0; l < NUM_LAYERS; l++) {
        const __nv_bfloat16* Wh = whi + (size_t)l * HIDDEN * HIDDEN;
        const __nv_bfloat16* Wl = wlo + (size_t)l * HIDDEN * HIDDEN;
        const float* Bl = bias + (size_t)l * HIDDEN;
        const __nv_bfloat16* sh = (l & 1) ? xhiB : xhiA;
        const __nv_bfloat16* sl = (l & 1) ? xloB : xloA;
        __nv_bfloat16* dh = (l & 1) ? xhiA : xhiB;
        __nv_bfloat16* dl = (l & 1) ? xloA : xloB;
        if (l == NUM_LAYERS - 1) {
            dense_mma<true><<<grid, THREADS, SMEM_ALLOC>>>(
                sh, sl, Wh, Wl, Bl, nullptr, nullptr, out);
        } else {
            dense_mma<false><<<grid, THREADS, SMEM_ALLOC>>>(
                sh, sl, Wh, Wl, Bl, dh, dl, nullptr);
        }
    }
}

// round 12
// speedup vs baseline: 3.1223x; 1.3043x over previous
#include <cuda_runtime.h>
#include <cuda_fp16.h>
#include <stdint.h>
#include <math.h>

#define HIDDEN      512
#define BATCH       16384
#define NUM_LAYERS  8
#define NUM_OUTPUTS 16

#define BM 128
#define BN 128
#define BK 32                 // k per smem tile (32 fp16 = 64B per row)
#define KTILES (HIDDEN / BK)  // 16
#define THREADS 512           // 16 warps: 4 (M) x 4 (N), warp tile 32x32
#define STAGES 3

#define ROWSTRIDE 80          // 64B data + 16B pad -> conflict-free ldmatrix
#define MAT_BYTES (128 * ROWSTRIDE)   // 10240 per matrix tile
#define NMATS 3               // xhi, xlo, w
#define BUF_BYTES (NMATS * MAT_BYTES) // 30720
#define OFF_BIAS  0
#define OFF_TILES 512
#define SMEM_ALLOC (OFF_TILES + STAGES * BUF_BYTES)   // 92672

#define WSCALE 4.419417382415922e-4f   // 0.01 / sqrt(512)
#define BSCALE 0.01f
#define GAIN   1.4142135623730951f
#define SLOPE  0.2f

// Device-global scratch (allocation-free): split activations + fp16 weights
__device__ __align__(16) __half g_xhiA[BATCH * HIDDEN];
__device__ __align__(16) __half g_xloA[BATCH * HIDDEN];
__device__ __align__(16) __half g_xhiB[BATCH * HIDDEN];
__device__ __align__(16) __half g_xloB[BATCH * HIDDEN];
__device__ __align__(16) __half g_wh[NUM_LAYERS * HIDDEN * HIDDEN];

// ---------------------------------------------------------------------------
__device__ __forceinline__ uint32_t smem_u32(const void* p) {
    uint32_t a;
    asm("{ .reg .u64 t; cvta.to.shared.u64 t, %1; cvt.u32.u64 %0, t; }"
        : "=r"(a) : "l"(p));
    return a;
}
__device__ __forceinline__ float h_round(float x) {
    return __half2float(__float2half_rn(x));
}
// pack two fp32 -> fp16x2 (a in low half)
__device__ __forceinline__ uint32_t pack_h2(float a, float b) {
    uint32_t r;
    asm("cvt.rn.f16x2.f32 %0, %1, %2;" : "=r"(r) : "f"(b), "f"(a));
    return r;
}
__device__ __forceinline__ float lrelu_gain(float t) {
    return (t > 0.f ? t : SLOPE * t) * GAIN;
}

#define CP_ASYNC16(dst, src) \
    asm volatile("cp.async.cg.shared.global [%0], [%1], 16;" :: "r"(dst), "l"(src))
#define CP_COMMIT() asm volatile("cp.async.commit_group;" ::: "memory")
#define CP_WAITG(n) asm volatile("cp.async.wait_group %0;" :: "n"(n) : "memory")

#define LDSM_X4(r0, r1, r2, r3, addr) \
    asm volatile("ldmatrix.sync.aligned.m8n8.x4.shared.b16 {%0,%1,%2,%3}, [%4];" \
                 : "=r"(r0), "=r"(r1), "=r"(r2), "=r"(r3) : "r"(addr))

#define MMA16816H(c, a, b0, b1) \
    asm volatile("mma.sync.aligned.m16n8k16.row.col.f32.f16.f16.f32 " \
                 "{%0,%1,%2,%3}, {%4,%5,%6,%7}, {%8,%9}, {%0,%1,%2,%3};" \
                 : "+f"((c)[0]), "+f"((c)[1]), "+f"((c)[2]), "+f"((c)[3]) \
                 : "r"((a)[0]), "r"((a)[1]), "r"((a)[2]), "r"((a)[3]), \
                   "r"(b0), "r"(b1))

// ---------------------------------------------------------------------------
// Convert all layer weights to raw fp16 (wscale applied in GEMM epilogue)
// ---------------------------------------------------------------------------
__global__ void conv_w_kernel(const float* __restrict__ W,
                              __half* __restrict__ wh) {
    int base = (blockIdx.x * blockDim.x + threadIdx.x) * 4;
    float4 w = *reinterpret_cast<const float4*>(W + base);
    *reinterpret_cast<uint2*>(&wh[base]) =
        make_uint2(pack_h2(w.x, w.y), pack_h2(w.z, w.w));
}

// ---------------------------------------------------------------------------
// Pixel norm, writing split fp16 activations (hi + residual lo)
// ---------------------------------------------------------------------------
__global__ void pixelnorm_split_kernel(const float* __restrict__ z,
                                       __half* __restrict__ xhi,
                                       __half* __restrict__ xlo) {
    int row  = blockIdx.x * blockDim.y + threadIdx.y;
    int lane = threadIdx.x;
    const float4* zr = reinterpret_cast<const float4*>(z + (size_t)row * HIDDEN);
    float4 v[4];
    float ss = 0.f;
#pragma unroll
    for (int i = 0; i < 4; i++) {
        v[i] = zr[lane + 32 * i];
        ss += v[i].x * v[i].x + v[i].y * v[i].y + v[i].z * v[i].z + v[i].w * v[i].w;
    }
#pragma unroll
    for (int off = 16; off > 0; off >>= 1)
        ss += __shfl_xor_sync(0xFFFFFFFFu, ss, off);
    float s = rsqrtf(ss * (1.0f / HIDDEN) + 1e-8f);
#pragma unroll
    for (int i = 0; i < 4; i++) {
        float x0 = v[i].x * s, x1 = v[i].y * s, x2 = v[i].z * s, x3 = v[i].w * s;
        float h0 = h_round(x0), h1 = h_round(x1);
        float h2 = h_round(x2), h3 = h_round(x3);
        int e = row * HIDDEN + (lane + 32 * i) * 4;
        *reinterpret_cast<uint2*>(&xhi[e]) =
            make_uint2(pack_h2(h0, h1), pack_h2(h2, h3));
        *reinterpret_cast<uint2*>(&xlo[e]) =
            make_uint2(pack_h2(x0 - h0, x1 - h1), pack_h2(x2 - h2, x3 - h3));
    }
}

// ---------------------------------------------------------------------------
// HMMA dense layer: acc = (Xhi + Xlo) @ Wraw^T  (fp32 accum, 2 MMAs/term)
// Y = lrelu(acc*wscale + b*bscale)*sqrt(2), re-split to fp16 hi/lo.
// 16 warps (4Mx4N), warp tile 32x32, BK=32, 3-stage cp.async ring,
// double-buffered register fragments.
// ---------------------------------------------------------------------------
template <bool BROADCAST>
__global__ __launch_bounds__(THREADS, 1)
void dense_mma(const __half* __restrict__ Xhi,
               const __half* __restrict__ Xlo,
               const __half* __restrict__ Wh,
               const float* __restrict__ Bv,
               __half* __restrict__ Yhi,
               __half* __restrict__ Ylo,
               float* __restrict__ Yout) {
    extern __shared__ char smem[];
    const uint32_t sbase = smem_u32(smem);
    float* bias_s = reinterpret_cast<float*>(smem + OFF_BIAS);

    const int tid  = threadIdx.x;
    const int wid  = tid >> 5;
    const int lane = tid & 31;
    const int mBase = blockIdx.y * BM;
    const int nBase = blockIdx.x * BN;
    const int wmBase = (wid & 3) * 32;   // warp M offset
    const int wnBase = (wid >> 2) * 32;  // warp N offset

    if (tid < BN) bias_s[tid] = Bv[nBase + tid] * BSCALE;

    const __half* srcs[NMATS] = {Xhi, Xlo, Wh};

    // one 16B chunk per matrix per thread per stage (512 chunks/matrix)
    auto load_tile = [&](int kt, int buf) {
        uint32_t base = sbase + OFF_TILES + buf * BUF_BYTES;
        int row = tid >> 2;          // 0..127
        int c   = tid & 3;           // 16B chunk within 64B row
        uint32_t soff = (uint32_t)(row * ROWSTRIDE + c * 16);
#pragma unroll
        for (int m = 0; m < NMATS; m++) {
            int rowG = (m < 2 ? mBase : nBase) + row;
            const __half* src =
                srcs[m] + (size_t)rowG * HIDDEN + kt * BK + c * 8;
            CP_ASYNC16(base + m * MAT_BYTES + soff, src);
        }
    };

    // per-warp ldsm address components (constant across steps)
    const uint32_t a_off0 =
        (uint32_t)((wmBase + (lane & 15)) * ROWSTRIDE + (lane >> 4) * 16);
    const int bg = lane >> 3, br = lane & 7;
    const uint32_t b_off0 =
        (uint32_t)((wnBase + (bg >> 1) * 8 + br) * ROWSTRIDE + (bg & 1) * 16);

    auto load_frags = [&](int buf, int s,
                          uint32_t aH[2][4], uint32_t aL[2][4],
                          uint32_t bW[4][2]) {
        const uint32_t xb    = sbase + OFF_TILES + buf * BUF_BYTES;
        const uint32_t xhi_b = xb;
        const uint32_t xlo_b = xb + MAT_BYTES;
        const uint32_t w_b   = xb + 2 * MAT_BYTES;
        const uint32_t sk = (uint32_t)(2 * s * 16);
#pragma unroll
        for (int mi = 0; mi < 2; mi++) {
            uint32_t ad = a_off0 + sk + mi * 16 * ROWSTRIDE;
            LDSM_X4(aH[mi][0], aH[mi][1], aH[mi][2], aH[mi][3], xhi_b + ad);
            LDSM_X4(aL[mi][0], aL[mi][1], aL[mi][2], aL[mi][3], xlo_b + ad);
        }
#pragma unroll
        for (int p = 0; p < 2; p++) {
            uint32_t bd = b_off0 + sk + p * 16 * ROWSTRIDE;
            LDSM_X4(bW[2 * p][0], bW[2 * p][1], bW[2 * p + 1][0],
                    bW[2 * p + 1][1], w_b + bd);
        }
    };

    float c[2][4][4];
#pragma unroll
    for (int mi = 0; mi < 2; mi++)
#pragma unroll
        for (int ni = 0; ni < 4; ni++)
#pragma unroll
            for (int j = 0; j < 4; j++) c[mi][ni][j] = 0.f;

    auto do_mma = [&](uint32_t aH[2][4], uint32_t aL[2][4], uint32_t bW[4][2]) {
#pragma unroll
        for (int mi = 0; mi < 2; mi++)
#pragma unroll
            for (int ni = 0; ni < 4; ni++) {
                MMA16816H(c[mi][ni], aH[mi], bW[ni][0], bW[ni][1]);
                MMA16816H(c[mi][ni], aL[mi], bW[ni][0], bW[ni][1]);
            }
    };

    uint32_t aH[2][2][4], aL[2][2][4], bW[2][4][2];

    load_tile(0, 0); CP_COMMIT();
    load_tile(1, 1); CP_COMMIT();
    CP_WAITG(1);            // tile 0 resident
    __syncthreads();
    load_frags(0, 0, aH[0], aL[0], bW[0]);

    for (int kt = 0; kt < KTILES; kt++) {
        const int buf = kt % STAGES;

        // LDSMs for step 1 issue before MMAs of step 0 -> latency hidden
        load_frags(buf, 1, aH[1], aL[1], bW[1]);
        do_mma(aH[0], aL[0], bW[0]);

        if (kt + 2 < KTILES) {          // prefetch tile kt+2 (3rd buffer: free)
            load_tile(kt + 2, (kt + 2) % STAGES);
            CP_COMMIT();
        }
        if (kt + 1 < KTILES) {
            if (kt + 2 < KTILES) CP_WAITG(1); else CP_WAITG(0);  // tile kt+1 in
            __syncthreads();            // all warps done reading tile kt
            load_frags((kt + 1) % STAGES, 0, aH[0], aL[0], bW[0]);
        }
        do_mma(aH[1], aL[1], bW[1]);
    }

    // ---- epilogue ----
    if (BROADCAST) {
        // stage fp32 tile in smem (reuse tile buffers), then coalesced float4
        __syncthreads();
        float* stage = reinterpret_cast<float*>(smem + OFF_TILES);
        const int LDSTG = 132;   // padded fp32 row stride (128*132*4 = 67584 B)
#pragma unroll
        for (int mi = 0; mi < 2; mi++) {
            int r0 = wmBase + mi * 16 + (lane >> 2);
#pragma unroll
            for (int ni = 0; ni < 4; ni++) {
                int n = wnBase + ni * 8 + (lane & 3) * 2;
                stage[r0 * LDSTG + n] =
                    lrelu_gain(c[mi][ni][0] * WSCALE + bias_s[n]);
                stage[r0 * LDSTG + n + 1] =
                    lrelu_gain(c[mi][ni][1] * WSCALE + bias_s[n + 1]);
                stage[(r0 + 8) * LDSTG + n] =
                    lrelu_gain(c[mi][ni][2] * WSCALE + bias_s[n]);
                stage[(r0 + 8) * LDSTG + n + 1] =
                    lrelu_gain(c[mi][ni][3] * WSCALE + bias_s[n + 1]);
            }
        }
        __syncthreads();
        // 128 rows x 16 reps x 32 float4-cols, 512 threads -> 128 iters
        for (int it = tid; it < 128 * NUM_OUTPUTS * 32; it += THREADS) {
            int col4 = it & 31;
            int rep  = (it >> 5) & 15;
            int row  = it >> 9;
            float4 v = *reinterpret_cast<const float4*>(
                &stage[row * LDSTG + col4 * 4]);
            *reinterpret_cast<float4*>(
                Yout + ((size_t)(mBase + row) * NUM_OUTPUTS + rep) * HIDDEN
                     + nBase + col4 * 4) = v;
        }
    } else {
#pragma unroll
        for (int mi = 0; mi < 2; mi++) {
            int m0 = mBase + wmBase + mi * 16 + (lane >> 2);
#pragma unroll
            for (int ni = 0; ni < 4; ni++) {
                int n = nBase + wnBase + ni * 8 + (lane & 3) * 2;
                float v0 = lrelu_gain(c[mi][ni][0] * WSCALE + bias_s[n - nBase]);
                float v1 = lrelu_gain(c[mi][ni][1] * WSCALE + bias_s[n - nBase + 1]);
                float v2 = lrelu_gain(c[mi][ni][2] * WSCALE + bias_s[n - nBase]);
                float v3 = lrelu_gain(c[mi][ni][3] * WSCALE + bias_s[n - nBase + 1]);
                float h0 = h_round(v0), h1 = h_round(v1);
                float h2 = h_round(v2), h3 = h_round(v3);
                size_t e0 = (size_t)m0 * HIDDEN + n;
                size_t e1 = e0 + (size_t)8 * HIDDEN;
                *reinterpret_cast<uint32_t*>(&Yhi[e0]) = pack_h2(h0, h1);
                *reinterpret_cast<uint32_t*>(&Ylo[e0]) = pack_h2(v0 - h0, v1 - h1);
                *reinterpret_cast<uint32_t*>(&Yhi[e1]) = pack_h2(h2, h3);
                *reinterpret_cast<uint32_t*>(&Ylo[e1]) = pack_h2(v2 - h2, v3 - h3);
            }
        }
    }
}

// ---------------------------------------------------------------------------
extern "C" void kernel_launch(void* const* d_in, const int* in_sizes, int n_in,
                              void* d_out, int out_size) {
    const float* z      = (const float*)d_in[0];
    const float* weight = (const float*)d_in[1];
    const float* bias   = (const float*)d_in[2];
    float* out          = (float*)d_out;

    __half *xhiA, *xloA, *xhiB, *xloB, *wh;
    cudaGetSymbolAddress((void**)&xhiA, g_xhiA);
    cudaGetSymbolAddress((void**)&xloA, g_xloA);
    cudaGetSymbolAddress((void**)&xhiB, g_xhiB);
    cudaGetSymbolAddress((void**)&xloB, g_xloB);
    cudaGetSymbolAddress((void**)&wh, g_wh);

    cudaFuncSetAttribute(dense_mma<false>,
                         cudaFuncAttributeMaxDynamicSharedMemorySize, SMEM_ALLOC);
    cudaFuncSetAttribute(dense_mma<true>,
                         cudaFuncAttributeMaxDynamicSharedMemorySize, SMEM_ALLOC);

    // 1) convert all weights to raw fp16 (wscale folded into epilogue)
    conv_w_kernel<<<NUM_LAYERS * HIDDEN * HIDDEN / (256 * 4), 256>>>(weight, wh);

    // 2) pixel norm -> split fp16 activations (buffer A)
    pixelnorm_split_kernel<<<BATCH / 8, dim3(32, 8)>>>(z, xhiA, xloA);

    // 3) 8 HMMA dense layers, ping-pong; last broadcasts into wp
    dim3 grid(HIDDEN / BN, BATCH / BM);  // (4, 128)
    for (int l = 0; l < NUM_LAYERS; l++) {
        const __half* Wl = wh + (size_t)l * HIDDEN * HIDDEN;
        const float* Bl = bias + (size_t)l * HIDDEN;
        const __half* sh = (l & 1) ? xhiB : xhiA;
        const __half* sl = (l & 1) ? xloB : xloA;
        __half* dh = (l & 1) ? xhiA : xhiB;
        __half* dl = (l & 1) ? xloA : xloB;
        if (l == NUM_LAYERS - 1) {
            dense_mma<true><<<grid, THREADS, SMEM_ALLOC>>>(
                sh, sl, Wl, Bl, nullptr, nullptr, out);
        } else {
            dense_mma<false><<<grid, THREADS, SMEM_ALLOC>>>(
                sh, sl, Wl, Bl, dh, dl, nullptr);
        }
    }
}

// round 14
// speedup vs baseline: 4.7165x; 1.5106x over previous
#include <cuda_runtime.h>
#include <cuda_fp16.h>
#include <stdint.h>
#include <math.h>

#define HIDDEN      512
#define BATCH       16384
#define NUM_LAYERS  8
#define NUM_OUTPUTS 16

#define BM 128
#define BN 128
#define BK 32                 // k per smem tile (32 fp16 = 64B per row)
#define KTILES (HIDDEN / BK)  // 16
#define THREADS 512           // 16 warps: 4 (M) x 4 (N), warp tile 32x32
#define STAGES 3

#define ROWSTRIDE 80          // 64B data + 16B pad -> conflict-free ldmatrix
#define MAT_BYTES (128 * ROWSTRIDE)   // 10240 per matrix tile
#define NMATS 2               // x, w
#define BUF_BYTES (NMATS * MAT_BYTES) // 20480
#define OFF_BIAS  0
#define OFF_TILES 512
#define SMEM_TILES (OFF_TILES + STAGES * BUF_BYTES)     // 61952
#define SMEM_STAGE (OFF_TILES + 128 * 132 * 4)          // 68096 (bcast epilogue)
#define SMEM_ALLOC (SMEM_STAGE > SMEM_TILES ? SMEM_STAGE : SMEM_TILES)

#define WSCALE 4.419417382415922e-4f   // 0.01 / sqrt(512)
#define BSCALE 0.01f
#define GAIN   1.4142135623730951f
#define SLOPE  0.2f

// Device-global scratch (allocation-free): fp16 activations + fp16 weights
__device__ __align__(16) __half g_xA[BATCH * HIDDEN];
__device__ __align__(16) __half g_xB[BATCH * HIDDEN];
__device__ __align__(16) __half g_wh[NUM_LAYERS * HIDDEN * HIDDEN];

// ---------------------------------------------------------------------------
__device__ __forceinline__ uint32_t smem_u32(const void* p) {
    uint32_t a;
    asm("{ .reg .u64 t; cvta.to.shared.u64 t, %1; cvt.u32.u64 %0, t; }"
        : "=r"(a) : "l"(p));
    return a;
}
// pack two fp32 -> fp16x2 (a in low half)
__device__ __forceinline__ uint32_t pack_h2(float a, float b) {
    uint32_t r;
    asm("cvt.rn.f16x2.f32 %0, %1, %2;" : "=r"(r) : "f"(b), "f"(a));
    return r;
}
__device__ __forceinline__ float lrelu_gain(float t) {
    return (t > 0.f ? t : SLOPE * t) * GAIN;
}

#define CP_ASYNC16(dst, src) \
    asm volatile("cp.async.cg.shared.global [%0], [%1], 16;" :: "r"(dst), "l"(src))
#define CP_COMMIT() asm volatile("cp.async.commit_group;" ::: "memory")
#define CP_WAITG(n) asm volatile("cp.async.wait_group %0;" :: "n"(n) : "memory")

#define LDSM_X4(r0, r1, r2, r3, addr) \
    asm volatile("ldmatrix.sync.aligned.m8n8.x4.shared.b16 {%0,%1,%2,%3}, [%4];" \
                 : "=r"(r0), "=r"(r1), "=r"(r2), "=r"(r3) : "r"(addr))

#define MMA16816H(c, a, b0, b1) \
    asm volatile("mma.sync.aligned.m16n8k16.row.col.f32.f16.f16.f32 " \
                 "{%0,%1,%2,%3}, {%4,%5,%6,%7}, {%8,%9}, {%0,%1,%2,%3};" \
                 : "+f"((c)[0]), "+f"((c)[1]), "+f"((c)[2]), "+f"((c)[3]) \
                 : "r"((a)[0]), "r"((a)[1]), "r"((a)[2]), "r"((a)[3]), \
                   "r"(b0), "r"(b1))

// ---------------------------------------------------------------------------
// Convert all layer weights to raw fp16 (wscale applied in GEMM epilogue)
// ---------------------------------------------------------------------------
__global__ void conv_w_kernel(const float* __restrict__ W,
                              __half* __restrict__ wh) {
    int base = (blockIdx.x * blockDim.x + threadIdx.x) * 4;
    float4 w = *reinterpret_cast<const float4*>(W + base);
    *reinterpret_cast<uint2*>(&wh[base]) =
        make_uint2(pack_h2(w.x, w.y), pack_h2(w.z, w.w));
}

// ---------------------------------------------------------------------------
// Pixel norm -> fp16 activations
// ---------------------------------------------------------------------------
__global__ void pixelnorm_kernel(const float* __restrict__ z,
                                 __half* __restrict__ x) {
    int row  = blockIdx.x * blockDim.y + threadIdx.y;
    int lane = threadIdx.x;
    const float4* zr = reinterpret_cast<const float4*>(z + (size_t)row * HIDDEN);
    float4 v[4];
    float ss = 0.f;
#pragma unroll
    for (int i = 0; i < 4; i++) {
        v[i] = zr[lane + 32 * i];
        ss += v[i].x * v[i].x + v[i].y * v[i].y + v[i].z * v[i].z + v[i].w * v[i].w;
    }
#pragma unroll
    for (int off = 16; off > 0; off >>= 1)
        ss += __shfl_xor_sync(0xFFFFFFFFu, ss, off);
    float s = rsqrtf(ss * (1.0f / HIDDEN) + 1e-8f);
#pragma unroll
    for (int i = 0; i < 4; i++) {
        int e = row * HIDDEN + (lane + 32 * i) * 4;
        *reinterpret_cast<uint2*>(&x[e]) =
            make_uint2(pack_h2(v[i].x * s, v[i].y * s),
                       pack_h2(v[i].z * s, v[i].w * s));
    }
}

// ---------------------------------------------------------------------------
// HMMA dense layer: acc = X @ Wraw^T (fp16 in, fp32 accum, 1 MMA term)
// Y = lrelu(acc*wscale + b*bscale)*sqrt(2) -> fp16 (or fp32 broadcast).
// 16 warps (4Mx4N), warp tile 32x32, BK=32, 3-stage cp.async ring,
// double-buffered register fragments.
// ---------------------------------------------------------------------------
template <bool BROADCAST>
__global__ __launch_bounds__(THREADS, 1)
void dense_mma(const __half* __restrict__ X,
               const __half* __restrict__ Wh,
               const float* __restrict__ Bv,
               __half* __restrict__ Y,
               float* __restrict__ Yout) {
    extern __shared__ char smem[];
    const uint32_t sbase = smem_u32(smem);
    float* bias_s = reinterpret_cast<float*>(smem + OFF_BIAS);

    const int tid  = threadIdx.x;
    const int wid  = tid >> 5;
    const int lane = tid & 31;
    const int mBase = blockIdx.y * BM;
    const int nBase = blockIdx.x * BN;
    const int wmBase = (wid & 3) * 32;   // warp M offset
    const int wnBase = (wid >> 2) * 32;  // warp N offset

    if (tid < BN) bias_s[tid] = Bv[nBase + tid] * BSCALE;

    const __half* srcs[NMATS] = {X, Wh};

    // one 16B chunk per matrix per thread per stage (512 chunks/matrix)
    auto load_tile = [&](int kt, int buf) {
        uint32_t base = sbase + OFF_TILES + buf * BUF_BYTES;
        int row = tid >> 2;          // 0..127
        int c   = tid & 3;           // 16B chunk within 64B row
        uint32_t soff = (uint32_t)(row * ROWSTRIDE + c * 16);
#pragma unroll
        for (int m = 0; m < NMATS; m++) {
            int rowG = (m == 0 ? mBase : nBase) + row;
            const __half* src =
                srcs[m] + (size_t)rowG * HIDDEN + kt * BK + c * 8;
            CP_ASYNC16(base + m * MAT_BYTES + soff, src);
        }
    };

    // per-warp ldsm address components (constant across steps)
    const uint32_t a_off0 =
        (uint32_t)((wmBase + (lane & 15)) * ROWSTRIDE + (lane >> 4) * 16);
    const int bg = lane >> 3, br = lane & 7;
    const uint32_t b_off0 =
        (uint32_t)((wnBase + (bg >> 1) * 8 + br) * ROWSTRIDE + (bg & 1) * 16);

    auto load_frags = [&](int buf, int s, uint32_t aF[2][4], uint32_t bW[4][2]) {
        const uint32_t xb  = sbase + OFF_TILES + buf * BUF_BYTES;
        const uint32_t x_b = xb;
        const uint32_t w_b = xb + MAT_BYTES;
        const uint32_t sk  = (uint32_t)(2 * s * 16);
#pragma unroll
        for (int mi = 0; mi < 2; mi++) {
            uint32_t ad = a_off0 + sk + mi * 16 * ROWSTRIDE;
            LDSM_X4(aF[mi][0], aF[mi][1], aF[mi][2], aF[mi][3], x_b + ad);
        }
#pragma unroll
        for (int p = 0; p < 2; p++) {
            uint32_t bd = b_off0 + sk + p * 16 * ROWSTRIDE;
            LDSM_X4(bW[2 * p][0], bW[2 * p][1], bW[2 * p + 1][0],
                    bW[2 * p + 1][1], w_b + bd);
        }
    };

    float c[2][4][4];
#pragma unroll
    for (int mi = 0; mi < 2; mi++)
#pragma unroll
        for (int ni = 0; ni < 4; ni++)
#pragma unroll
            for (int j = 0; j < 4; j++) c[mi][ni][j] = 0.f;

    auto do_mma = [&](uint32_t aF[2][4], uint32_t bW[4][2]) {
#pragma unroll
        for (int mi = 0; mi < 2; mi++)
#pragma unroll
            for (int ni = 0; ni < 4; ni++)
                MMA16816H(c[mi][ni], aF[mi], bW[ni][0], bW[ni][1]);
    };

    uint32_t aF[2][2][4], bW[2][4][2];

    load_tile(0, 0); CP_COMMIT();
    load_tile(1, 1); CP_COMMIT();
    CP_WAITG(1);            // tile 0 resident
    __syncthreads();
    load_frags(0, 0, aF[0], bW[0]);

    for (int kt = 0; kt < KTILES; kt++) {
        const int buf = kt % STAGES;

        // LDSMs for step 1 issue before MMAs of step 0 -> latency hidden
        load_frags(buf, 1, aF[1], bW[1]);
        do_mma(aF[0], bW[0]);

        if (kt + 2 < KTILES) {          // prefetch tile kt+2 (3rd buffer: free)
            load_tile(kt + 2, (kt + 2) % STAGES);
            CP_COMMIT();
        }
        if (kt + 1 < KTILES) {
            if (kt + 2 < KTILES) CP_WAITG(1); else CP_WAITG(0);  // tile kt+1 in
            __syncthreads();            // all warps done reading tile kt
            load_frags((kt + 1) % STAGES, 0, aF[0], bW[0]);
        }
        do_mma(aF[1], bW[1]);
    }

    // ---- epilogue ----
    if (BROADCAST) {
        // stage fp32 tile in smem (reuse tile buffers), then coalesced float4
        __syncthreads();
        float* stage = reinterpret_cast<float*>(smem + OFF_TILES);
        const int LDSTG = 132;   // padded fp32 row stride
#pragma unroll
        for (int mi = 0; mi < 2; mi++) {
            int r0 = wmBase + mi * 16 + (lane >> 2);
#pragma unroll
            for (int ni = 0; ni < 4; ni++) {
                int n = wnBase + ni * 8 + (lane & 3) * 2;
                stage[r0 * LDSTG + n] =
                    lrelu_gain(c[mi][ni][0] * WSCALE + bias_s[n]);
                stage[r0 * LDSTG + n + 1] =
                    lrelu_gain(c[mi][ni][1] * WSCALE + bias_s[n + 1]);
                stage[(r0 + 8) * LDSTG + n] =
                    lrelu_gain(c[mi][ni][2] * WSCALE + bias_s[n]);
                stage[(r0 + 8) * LDSTG + n + 1] =
                    lrelu_gain(c[mi][ni][3] * WSCALE + bias_s[n + 1]);
            }
        }
        __syncthreads();
        // 128 rows x 16 reps x 32 float4-cols, 512 threads -> 128 iters
        for (int it = tid; it < 128 * NUM_OUTPUTS * 32; it += THREADS) {
            int col4 = it & 31;
            int rep  = (it >> 5) & 15;
            int row  = it >> 9;
            float4 v = *reinterpret_cast<const float4*>(
                &stage[row * LDSTG + col4 * 4]);
            *reinterpret_cast<float4*>(
                Yout + ((size_t)(mBase + row) * NUM_OUTPUTS + rep) * HIDDEN
                     + nBase + col4 * 4) = v;
        }
    } else {
#pragma unroll
        for (int mi = 0; mi < 2; mi++) {
            int m0 = mBase + wmBase + mi * 16 + (lane >> 2);
#pragma unroll
            for (int ni = 0; ni < 4; ni++) {
                int n = nBase + wnBase + ni * 8 + (lane & 3) * 2;
                float v0 = lrelu_gain(c[mi][ni][0] * WSCALE + bias_s[n - nBase]);
                float v1 = lrelu_gain(c[mi][ni][1] * WSCALE + bias_s[n - nBase + 1]);
                float v2 = lrelu_gain(c[mi][ni][2] * WSCALE + bias_s[n - nBase]);
                float v3 = lrelu_gain(c[mi][ni][3] * WSCALE + bias_s[n - nBase + 1]);
                size_t e0 = (size_t)m0 * HIDDEN + n;
                size_t e1 = e0 + (size_t)8 * HIDDEN;
                *reinterpret_cast<uint32_t*>(&Y[e0]) = pack_h2(v0, v1);
                *reinterpret_cast<uint32_t*>(&Y[e1]) = pack_h2(v2, v3);
            }
        }
    }
}

// ---------------------------------------------------------------------------
extern "C" void kernel_launch(void* const* d_in, const int* in_sizes, int n_in,
                              void* d_out, int out_size) {
    const float* z      = (const float*)d_in[0];
    const float* weight = (const float*)d_in[1];
    const float* bias   = (const float*)d_in[2];
    float* out          = (float*)d_out;

    __half *xA, *xB, *wh;
    cudaGetSymbolAddress((void**)&xA, g_xA);
    cudaGetSymbolAddress((void**)&xB, g_xB);
    cudaGetSymbolAddress((void**)&wh, g_wh);

    cudaFuncSetAttribute(dense_mma<false>,
                         cudaFuncAttributeMaxDynamicSharedMemorySize, SMEM_ALLOC);
    cudaFuncSetAttribute(dense_mma<true>,
                         cudaFuncAttributeMaxDynamicSharedMemorySize, SMEM_ALLOC);

    // 1) convert all weights to raw fp16 (wscale folded into epilogue)
    conv_w_kernel<<<NUM_LAYERS * HIDDEN * HIDDEN / (256 * 4), 256>>>(weight, wh);

    // 2) pixel norm -> fp16 activations (buffer A)
    pixelnorm_kernel<<<BATCH / 8, dim3(32, 8)>>>(z, xA);

    // 3) 8 HMMA dense layers, ping-pong; last broadcasts into wp
    dim3 grid(HIDDEN / BN, BATCH / BM);  // (4, 128)
    for (int l = 0; l < NUM_LAYERS; l++) {
        const __half* Wl = wh + (size_t)l * HIDDEN * HIDDEN;
        const float* Bl = bias + (size_t)l * HIDDEN;
        const __half* src = (l & 1) ? xB : xA;
        __half* dst       = (l & 1) ? xA : xB;
        if (l == NUM_LAYERS - 1) {
            dense_mma<true><<<grid, THREADS, SMEM_ALLOC>>>(
                src, Wl, Bl, nullptr, out);
        } else {
            dense_mma<false><<<grid, THREADS, SMEM_ALLOC>>>(
                src, Wl, Bl, dst, nullptr);
        }
    }
}